// round 1
// baseline (speedup 1.0000x reference)
#include <cuda_runtime.h>
#include <math.h>
#include <stdint.h>

#define BB 4
#define NN 32768
#define KK 128
#define MM 1024
#define CC 256
#define GG 32
#define HH 8
#define DD 32

// ---------------- scratch (device globals; no allocation allowed) ----------------
__device__ float g_spec1 [BB*KK*CC];
__device__ float g_spec1m[BB*KK*CC];
__device__ float g_spec2 [BB*KK*CC];
__device__ float g_spec2m[BB*KK*CC];
__device__ float g_xfar  [BB*MM*CC];
__device__ float g_q     [BB*MM*CC];
__device__ float g_kmat  [BB*MM*CC];
__device__ float g_v     [BB*MM*CC];
__device__ float g_ao    [BB*MM*CC];
__device__ float g_proj  [BB*MM*CC];
__device__ float g_gnm   [BB*GG];
__device__ float g_gnr   [BB*GG];

// ---------------- zero the atomic accumulators ----------------
__global__ void k_zero() {
    int i = blockIdx.x * blockDim.x + threadIdx.x;
    if (i < BB*KK*CC) { g_spec1[i] = 0.f; g_spec2[i] = 0.f; }
}

// ---------------- to_basis: spec[b,k,c] += sum_n E[b,row(n),k]*mass[row]*X[b,n,c]
// split over N chunks; atomicAdd into spec. Block computes [128 x 64] partial.
__global__ void k_tobasis(const float* __restrict__ X, const float* __restrict__ mass,
                          const float* __restrict__ evecs, const int* __restrict__ gidx,
                          float* __restrict__ spec, int chunk, int xRowsPerBatch)
{
    int b  = blockIdx.z;
    int c0 = blockIdx.y * 64;
    int n0 = blockIdx.x * chunk;
    __shared__ float Es[16][128];
    __shared__ float Xs[16][64];
    int tid = threadIdx.x;
    int ty = tid >> 4, tx = tid & 15;   // k = ty*8+i, c = tx*4+j

    float acc[8][4];
#pragma unroll
    for (int i = 0; i < 8; i++)
#pragma unroll
        for (int j = 0; j < 4; j++) acc[i][j] = 0.f;

    for (int nb = 0; nb < chunk; nb += 16) {
        // load 16 evecs rows (512 float4)
#pragma unroll
        for (int v = tid; v < 512; v += 256) {
            int r = v >> 5, c4 = v & 31;
            int n = n0 + nb + r;
            int rr = gidx ? gidx[b*MM + n] : n;
            reinterpret_cast<float4*>(&Es[r][0])[c4] =
                reinterpret_cast<const float4*>(&evecs[((size_t)b*NN + rr) * KK])[c4];
        }
        // load 16 x-rows (64 channels), scaled by mass
        {
            int r = tid >> 4, c4 = tid & 15;
            int n = n0 + nb + r;
            int rr = gidx ? gidx[b*MM + n] : n;
            float ms = mass[(size_t)b*NN + rr];
            float4 xv = reinterpret_cast<const float4*>(
                &X[((size_t)b*xRowsPerBatch + n) * CC + c0])[c4];
            xv.x *= ms; xv.y *= ms; xv.z *= ms; xv.w *= ms;
            reinterpret_cast<float4*>(&Xs[r][0])[c4] = xv;
        }
        __syncthreads();
#pragma unroll
        for (int r = 0; r < 16; r++) {
            float4 a0 = *reinterpret_cast<float4*>(&Es[r][ty*8]);
            float4 a1 = *reinterpret_cast<float4*>(&Es[r][ty*8 + 4]);
            float4 x0 = *reinterpret_cast<float4*>(&Xs[r][tx*4]);
            float a[8] = {a0.x,a0.y,a0.z,a0.w,a1.x,a1.y,a1.z,a1.w};
            float xb[4] = {x0.x,x0.y,x0.z,x0.w};
#pragma unroll
            for (int i = 0; i < 8; i++)
#pragma unroll
                for (int j = 0; j < 4; j++) acc[i][j] += a[i] * xb[j];
        }
        __syncthreads();
    }
#pragma unroll
    for (int i = 0; i < 8; i++)
#pragma unroll
        for (int j = 0; j < 4; j++)
            atomicAdd(&spec[((size_t)b*KK + ty*8 + i) * CC + c0 + tx*4 + j], acc[i][j]);
}

// ---------------- spectral coefficient multiply (+ optional out_w fold) ----------------
__global__ void k_coef(const float* __restrict__ evals, const float* __restrict__ tvec,
                       const float* __restrict__ specin, float* __restrict__ specout,
                       const float* __restrict__ outw)
{
    int bk = blockIdx.x;             // b*K + k
    int b = bk >> 7, k = bk & 127;
    int c = threadIdx.x;
    float t = fmaxf(tvec[c], 1e-8f);
    float w = outw ? fmaxf(outw[c], 1e-8f) : 1.f;
    specout[(size_t)bk*CC + c] = expf(-evals[b*KK + k] * t) * specin[(size_t)bk*CC + c] * w;
}

// ---------------- generic GEMM: out[b, r0+n, c0+c] = sum_k A[b,row(n),k]*W[b,k,c] (+bias)
// tile 64 rows x 128 cols, K chunks of 32
__global__ void k_gemm(const float* __restrict__ A, const float* __restrict__ W,
                       const float* __restrict__ bias, const int* __restrict__ gidx,
                       float* __restrict__ out, int Kd,
                       long aBatch, long wBatch, long oBatch)
{
    int b  = blockIdx.z;
    int r0 = blockIdx.x * 64;
    int c0 = blockIdx.y * 128;
    __shared__ float Et[32][68];    // Et[kk][n], stride 68 keeps float4 alignment
    __shared__ float Sc[32][132];   // Sc[kk][c]
    int tid = threadIdx.x;
    int an = tid >> 4;   // n group: rows an*4 .. +4
    int ac = tid & 15;   // c group: cols ac*8 .. +8
    float acc[4][8];
#pragma unroll
    for (int i = 0; i < 4; i++)
#pragma unroll
        for (int j = 0; j < 8; j++) acc[i][j] = 0.f;

    const float* Ab = A + (size_t)b * aBatch;
    const float* Wb = W + (size_t)b * wBatch;

    for (int kc = 0; kc < Kd; kc += 32) {
        // load A chunk transposed: 64 rows x 32 k
        {
            int rloc = tid & 63;
            int qq   = tid >> 6;  // 0..3 -> 8 k-cols each
            int grow = gidx ? gidx[b*MM + r0 + rloc] : (r0 + rloc);
            const float4* src = reinterpret_cast<const float4*>(
                Ab + (size_t)grow * Kd + kc + qq*8);
            float4 v0 = src[0], v1 = src[1];
            int cb = qq * 8;
            Et[cb+0][rloc] = v0.x; Et[cb+1][rloc] = v0.y;
            Et[cb+2][rloc] = v0.z; Et[cb+3][rloc] = v0.w;
            Et[cb+4][rloc] = v1.x; Et[cb+5][rloc] = v1.y;
            Et[cb+6][rloc] = v1.z; Et[cb+7][rloc] = v1.w;
        }
        // load W chunk: 32 rows x 128 cols (1024 float4, 4/thread)
#pragma unroll
        for (int i = 0; i < 4; i++) {
            int v = tid + i*256;
            int rk = v >> 5, c4 = v & 31;
            reinterpret_cast<float4*>(&Sc[rk][0])[c4] =
                reinterpret_cast<const float4*>(Wb + (size_t)(kc+rk)*CC + c0)[c4];
        }
        __syncthreads();
#pragma unroll
        for (int kk = 0; kk < 32; kk++) {
            float4 a4 = *reinterpret_cast<float4*>(&Et[kk][an*4]);
            float4 s0 = *reinterpret_cast<float4*>(&Sc[kk][ac*8]);
            float4 s1 = *reinterpret_cast<float4*>(&Sc[kk][ac*8 + 4]);
            float a[4] = {a4.x,a4.y,a4.z,a4.w};
            float s[8] = {s0.x,s0.y,s0.z,s0.w,s1.x,s1.y,s1.z,s1.w};
#pragma unroll
            for (int i = 0; i < 4; i++)
#pragma unroll
                for (int j = 0; j < 8; j++) acc[i][j] += a[i] * s[j];
        }
        __syncthreads();
    }
#pragma unroll
    for (int i = 0; i < 4; i++) {
        int rr = r0 + an*4 + i;
        size_t o = (size_t)b * oBatch + (size_t)rr * CC + c0 + ac*8;
        float bv[8];
#pragma unroll
        for (int j = 0; j < 8; j++)
            bv[j] = acc[i][j] + (bias ? bias[c0 + ac*8 + j] : 0.f);
        float4 w0 = {bv[0],bv[1],bv[2],bv[3]};
        float4 w1 = {bv[4],bv[5],bv[6],bv[7]};
        *reinterpret_cast<float4*>(&out[o])     = w0;
        *reinterpret_cast<float4*>(&out[o + 4]) = w1;
    }
}

// ---------------- GroupNorm stats: per (b,g) mean/rstd over M*8 values ----------------
__global__ void k_gnstats()
{
    int b = blockIdx.x >> 5, g = blockIdx.x & 31;
    int tid = threadIdx.x;
    float s = 0.f, s2 = 0.f;
    for (int e = tid; e < MM*8; e += 256) {
        int m = e >> 3, j = e & 7;
        float v = g_xfar[((size_t)(b*MM + m)) * CC + (g << 3) + j];
        s += v; s2 += v * v;
    }
    __shared__ float rs[256], rq[256];
    rs[tid] = s; rq[tid] = s2;
    __syncthreads();
    for (int o = 128; o > 0; o >>= 1) {
        if (tid < o) { rs[tid] += rs[tid+o]; rq[tid] += rq[tid+o]; }
        __syncthreads();
    }
    if (tid == 0) {
        float mean = rs[0] * (1.f/8192.f);
        float var  = rq[0] * (1.f/8192.f) - mean*mean;
        g_gnm[blockIdx.x] = mean;
        g_gnr[blockIdx.x] = rsqrtf(var + 1e-6f);
    }
}

// ---------------- GroupNorm apply (in place) ----------------
__global__ void k_gnapply(const float* __restrict__ gn_w, const float* __restrict__ gn_b)
{
    int i = blockIdx.x * blockDim.x + threadIdx.x;   // over 262144 float4s
    int base = i * 4;
    int c  = base & 255;
    int bm = base >> 8;
    int b  = bm >> 10;
    int g  = c >> 3;
    float mean = g_gnm[b*GG + g];
    float r    = g_gnr[b*GG + g];
    float4 v = *reinterpret_cast<float4*>(&g_xfar[base]);
    v.x = (v.x - mean) * r * gn_w[c+0] + gn_b[c+0];
    v.y = (v.y - mean) * r * gn_w[c+1] + gn_b[c+1];
    v.z = (v.z - mean) * r * gn_w[c+2] + gn_b[c+2];
    v.w = (v.w - mean) * r * gn_w[c+3] + gn_b[c+3];
    *reinterpret_cast<float4*>(&g_xfar[base]) = v;
}

// ---------------- flash attention: 64-query tiles, online softmax ----------------
__global__ void k_attn()
{
    int b = blockIdx.z, h = blockIdx.y, q0 = blockIdx.x * 64;
    __shared__ float Qs[64][32];
    __shared__ float Ks[64][32];
    __shared__ float Vs[64][32];
    __shared__ float Ps[64][65];
    __shared__ float redm[4][64];
    __shared__ float redl[4][64];
    int tid = threadIdx.x;
    int q  = tid & 63;
    int cg = tid >> 6;   // 0..3

    // load Q tile
    for (int v = tid; v < 512; v += 256) {
        int r = v >> 3, d4 = v & 7;
        reinterpret_cast<float4*>(&Qs[r][0])[d4] =
            *reinterpret_cast<const float4*>(&g_q[((size_t)(b*MM) + q0 + r) * CC + h*DD + d4*4]);
    }
    __syncthreads();
    float qreg[32];
#pragma unroll
    for (int d = 0; d < 32; d += 4) {
        float4 t = *reinterpret_cast<float4*>(&Qs[q][d]);
        qreg[d] = t.x; qreg[d+1] = t.y; qreg[d+2] = t.z; qreg[d+3] = t.w;
    }
    float orun[8];
#pragma unroll
    for (int j = 0; j < 8; j++) orun[j] = 0.f;
    float mrun = -1e30f, lrun = 0.f;
    const float scale = 0.17677669529663687f;   // 1/sqrt(32)

    for (int kt = 0; kt < 16; kt++) {
        __syncthreads();   // previous PV done before overwriting Ks/Vs
        for (int v = tid; v < 512; v += 256) {
            int r = v >> 3, d4 = v & 7;
            size_t gi = ((size_t)b*MM + kt*64 + r) * CC + h*DD + d4*4;
            reinterpret_cast<float4*>(&Ks[r][0])[d4] =
                *reinterpret_cast<const float4*>(&g_kmat[gi]);
            reinterpret_cast<float4*>(&Vs[r][0])[d4] =
                *reinterpret_cast<const float4*>(&g_v[gi]);
        }
        __syncthreads();

        float s[16];
        float lm = -1e30f;
#pragma unroll
        for (int kk = 0; kk < 16; kk++) {
            int ki = cg*16 + kk;
            float a = 0.f;
#pragma unroll
            for (int d4 = 0; d4 < 8; d4++) {
                float4 k4 = *reinterpret_cast<float4*>(&Ks[ki][d4*4]);
                a += qreg[d4*4+0]*k4.x + qreg[d4*4+1]*k4.y
                   + qreg[d4*4+2]*k4.z + qreg[d4*4+3]*k4.w;
            }
            s[kk] = a * scale;
            lm = fmaxf(lm, s[kk]);
        }
        redm[cg][q] = lm;
        __syncthreads();
        float mt = fmaxf(fmaxf(redm[0][q], redm[1][q]), fmaxf(redm[2][q], redm[3][q]));
        float mnew = fmaxf(mrun, mt);
        float lsum = 0.f;
#pragma unroll
        for (int kk = 0; kk < 16; kk++) { s[kk] = expf(s[kk] - mnew); lsum += s[kk]; }
        redl[cg][q] = lsum;
#pragma unroll
        for (int kk = 0; kk < 16; kk++) Ps[q][cg*16 + kk] = s[kk];
        __syncthreads();
        float ltile = redl[0][q] + redl[1][q] + redl[2][q] + redl[3][q];
        float corr  = expf(mrun - mnew);
        lrun = lrun * corr + ltile;
#pragma unroll
        for (int j = 0; j < 8; j++) orun[j] *= corr;
#pragma unroll
        for (int k2 = 0; k2 < 64; k2++) {
            float p = Ps[q][k2];
            float4 v0 = *reinterpret_cast<float4*>(&Vs[k2][cg*8]);
            float4 v1 = *reinterpret_cast<float4*>(&Vs[k2][cg*8 + 4]);
            orun[0] += p*v0.x; orun[1] += p*v0.y; orun[2] += p*v0.z; orun[3] += p*v0.w;
            orun[4] += p*v1.x; orun[5] += p*v1.y; orun[6] += p*v1.z; orun[7] += p*v1.w;
        }
        mrun = mnew;
    }
    float inv = 1.f / lrun;
    size_t o = ((size_t)(b*MM) + q0 + q) * CC + h*DD + cg*8;
    float4 w0 = {orun[0]*inv, orun[1]*inv, orun[2]*inv, orun[3]*inv};
    float4 w1 = {orun[4]*inv, orun[5]*inv, orun[6]*inv, orun[7]*inv};
    *reinterpret_cast<float4*>(&g_ao[o])     = w0;
    *reinterpret_cast<float4*>(&g_ao[o + 4]) = w1;
}

// ---------------- launch ----------------
extern "C" void kernel_launch(void* const* d_in, const int* in_sizes, int n_in,
                              void* d_out, int out_size)
{
    const float* x       = (const float*)d_in[0];
    const float* mass    = (const float*)d_in[1];
    const float* evals   = (const float*)d_in[2];
    const float* evecs   = (const float*)d_in[3];
    const int*   far_idx = (const int*)  d_in[4];
    const float* t_in    = (const float*)d_in[5];
    const float* t_out   = (const float*)d_in[6];
    const float* gn_w    = (const float*)d_in[7];
    const float* gn_b    = (const float*)d_in[8];
    const float* Wq      = (const float*)d_in[9];
    const float* bq      = (const float*)d_in[10];
    const float* Wk      = (const float*)d_in[11];
    const float* bk      = (const float*)d_in[12];
    const float* Wv      = (const float*)d_in[13];
    const float* bv      = (const float*)d_in[14];
    const float* Wo      = (const float*)d_in[15];
    const float* bo      = (const float*)d_in[16];
    const float* out_w   = (const float*)d_in[17];
    float* out = (float*)d_out;

    float *p_spec1, *p_spec1m, *p_spec2, *p_spec2m, *p_xfar, *p_q, *p_k, *p_v, *p_ao, *p_proj;
    cudaGetSymbolAddress((void**)&p_spec1,  g_spec1);
    cudaGetSymbolAddress((void**)&p_spec1m, g_spec1m);
    cudaGetSymbolAddress((void**)&p_spec2,  g_spec2);
    cudaGetSymbolAddress((void**)&p_spec2m, g_spec2m);
    cudaGetSymbolAddress((void**)&p_xfar,   g_xfar);
    cudaGetSymbolAddress((void**)&p_q,      g_q);
    cudaGetSymbolAddress((void**)&p_k,      g_kmat);
    cudaGetSymbolAddress((void**)&p_v,      g_v);
    cudaGetSymbolAddress((void**)&p_ao,     g_ao);
    cudaGetSymbolAddress((void**)&p_proj,   g_proj);

    const long AKC = (long)KK * CC;     // spec batch stride
    const long AMC = (long)MM * CC;
    const long ANK = (long)NN * KK;
    const long ANC = (long)NN * CC;

    k_zero<<<512, 256>>>();

    // to_basis 1: full N, split-K over 16 chunks of 2048
    k_tobasis<<<dim3(16, 4, BB), 256>>>(x, mass, evecs, nullptr, p_spec1, 2048, NN);
    k_coef<<<BB*KK, CC>>>(evals, t_in, p_spec1, p_spec1m, nullptr);

    // from_basis 1: only the M gathered rows
    k_gemm<<<dim3(MM/64, 2, BB), 256>>>(evecs, p_spec1m, nullptr, far_idx,
                                        p_xfar, KK, ANK, AKC, AMC);

    // GroupNorm
    k_gnstats<<<BB*GG, 256>>>();
    k_gnapply<<<(BB*MM*CC/4)/256, 256>>>(gn_w, gn_b);

    // QKV projections
    k_gemm<<<dim3(BB*MM/64 / BB, 2, BB), 256>>>(p_xfar, Wq, bq, nullptr, p_q, CC, AMC, 0, AMC);
    k_gemm<<<dim3(MM/64, 2, BB), 256>>>(p_xfar, Wk, bk, nullptr, p_k, CC, AMC, 0, AMC);
    k_gemm<<<dim3(MM/64, 2, BB), 256>>>(p_xfar, Wv, bv, nullptr, p_v, CC, AMC, 0, AMC);

    // attention
    k_attn<<<dim3(MM/64, HH, BB), 256>>>();

    // output projection
    k_gemm<<<dim3(MM/64, 2, BB), 256>>>(p_ao, Wo, bo, nullptr, p_proj, CC, AMC, 0, AMC);

    // to_basis 2: only the M scattered rows
    k_tobasis<<<dim3(8, 4, BB), 256>>>(p_proj, mass, evecs, far_idx, p_spec2, 128, MM);
    k_coef<<<BB*KK, CC>>>(evals, t_out, p_spec2, p_spec2m, out_w);

    // from_basis 2: full N output (out_w folded into spec2m)
    k_gemm<<<dim3(NN/64, 2, BB), 256>>>(evecs, p_spec2m, nullptr, nullptr,
                                        out, KK, ANK, AKC, ANC);
}

// round 4
// speedup vs baseline: 1.1991x; 1.1991x over previous
#include <cuda_runtime.h>
#include <math.h>
#include <stdint.h>

#define BB 4
#define NN 32768
#define KK 128
#define MM 1024
#define CC 256
#define GG 32
#define HH 8
#define DD 32

// ---------------- scratch (device globals; no allocation allowed) ----------------
__device__ float g_spec1 [BB*KK*CC];
__device__ float g_spec1m[BB*KK*CC];
__device__ float g_spec2 [BB*KK*CC];
__device__ float g_spec2m[BB*KK*CC];
__device__ float g_xfar  [BB*MM*CC];
__device__ float g_q     [BB*MM*CC];
__device__ float g_kmat  [BB*MM*CC];
__device__ float g_v     [BB*MM*CC];
__device__ float g_ao    [BB*MM*CC];
__device__ float g_proj  [BB*MM*CC];
__device__ float g_gnm   [BB*GG];
__device__ float g_gnr   [BB*GG];

// ---------------- tf32 helpers ----------------
__device__ __forceinline__ float tf32r(float x) {
    uint32_t u; asm("cvt.rna.tf32.f32 %0, %1;" : "=r"(u) : "f"(x));
    return __uint_as_float(u);
}

__device__ __forceinline__ void mma8(float d[4], const uint32_t a[4],
                                     uint32_t b0, uint32_t b1) {
    asm volatile(
        "mma.sync.aligned.m16n8k8.row.col.f32.tf32.tf32.f32 "
        "{%0,%1,%2,%3},{%4,%5,%6,%7},{%8,%9},{%0,%1,%2,%3};\n"
        : "+f"(d[0]), "+f"(d[1]), "+f"(d[2]), "+f"(d[3])
        : "r"(a[0]), "r"(a[1]), "r"(a[2]), "r"(a[3]), "r"(b0), "r"(b1));
}

// ---------------- zero the atomic accumulators ----------------
__global__ void k_zero() {
    int i = blockIdx.x * blockDim.x + threadIdx.x;
    if (i < BB*KK*CC) { g_spec1[i] = 0.f; g_spec2[i] = 0.f; }
}

// =====================================================================
// to_basis via 3x-tf32 mma: spec[b,k,c] += sum_n E[b,row(n),k]*mass*X[b,n,c]
// block: 128 (k_spec) x 64 (c); split-K over N chunks, atomicAdd epilogue.
// A operand (m=k_spec, kfrag=n) = Es[n][k]; B operand (kfrag=n, n=c) = Xs[n][c]
// =====================================================================
__global__ void __launch_bounds__(256) k_tobasis_mma(
    const float* __restrict__ X, const float* __restrict__ mass,
    const float* __restrict__ evecs, const int* __restrict__ gidx,
    float* __restrict__ spec, int chunk, int xRowsPerBatch)
{
    int b  = blockIdx.z;
    int c0 = blockIdx.y * 64;
    int n0 = blockIdx.x * chunk;
    __shared__ float Ehi[16][132], Elo[16][132];
    __shared__ float Xhi[16][68],  Xlo[16][68];
    int tid  = threadIdx.x;
    int wid  = tid >> 5, lane = tid & 31;
    int wm   = wid & 3;          // 4 warps over k_spec (32 each)
    int wn   = wid >> 2;         // 2 warps over c (32 each)
    int lrow = lane >> 2;        // 0..7
    int lcol = lane & 3;         // 0..3

    float acc[2][4][4];
#pragma unroll
    for (int mt = 0; mt < 2; mt++)
#pragma unroll
        for (int nt = 0; nt < 4; nt++)
#pragma unroll
            for (int j = 0; j < 4; j++) acc[mt][nt][j] = 0.f;

    for (int nb = 0; nb < chunk; nb += 16) {
        // load 16 evecs rows (16 x 128), split hi/lo
#pragma unroll
        for (int v = tid; v < 512; v += 256) {
            int r = v >> 5, c4 = v & 31;
            int n = n0 + nb + r;
            int rr = gidx ? gidx[b*MM + n] : n;
            float4 e = *reinterpret_cast<const float4*>(
                &evecs[((size_t)b*NN + rr) * KK + c4*4]);
            float4 h, l;
            h.x = tf32r(e.x); l.x = tf32r(e.x - h.x);
            h.y = tf32r(e.y); l.y = tf32r(e.y - h.y);
            h.z = tf32r(e.z); l.z = tf32r(e.z - h.z);
            h.w = tf32r(e.w); l.w = tf32r(e.w - h.w);
            *reinterpret_cast<float4*>(&Ehi[r][c4*4]) = h;
            *reinterpret_cast<float4*>(&Elo[r][c4*4]) = l;
        }
        // load 16 x-rows (64 channels), scale by mass, split hi/lo
        {
            int r = tid >> 4, c4 = tid & 15;
            int n = n0 + nb + r;
            int rr = gidx ? gidx[b*MM + n] : n;
            float ms = mass[(size_t)b*NN + rr];
            float4 xv = *reinterpret_cast<const float4*>(
                &X[((size_t)b*xRowsPerBatch + n) * CC + c0 + c4*4]);
            xv.x *= ms; xv.y *= ms; xv.z *= ms; xv.w *= ms;
            float4 h, l;
            h.x = tf32r(xv.x); l.x = tf32r(xv.x - h.x);
            h.y = tf32r(xv.y); l.y = tf32r(xv.y - h.y);
            h.z = tf32r(xv.z); l.z = tf32r(xv.z - h.z);
            h.w = tf32r(xv.w); l.w = tf32r(xv.w - h.w);
            *reinterpret_cast<float4*>(&Xhi[r][c4*4]) = h;
            *reinterpret_cast<float4*>(&Xlo[r][c4*4]) = l;
        }
        __syncthreads();
#pragma unroll
        for (int ks = 0; ks < 2; ks++) {
            int kf = ks*8 + lcol;
            uint32_t Aih[2][4], Ail[2][4];
#pragma unroll
            for (int mt = 0; mt < 2; mt++) {
                int m = wm*32 + mt*16 + lrow;
                Aih[mt][0] = __float_as_uint(Ehi[kf  ][m]);
                Aih[mt][1] = __float_as_uint(Ehi[kf  ][m+8]);
                Aih[mt][2] = __float_as_uint(Ehi[kf+4][m]);
                Aih[mt][3] = __float_as_uint(Ehi[kf+4][m+8]);
                Ail[mt][0] = __float_as_uint(Elo[kf  ][m]);
                Ail[mt][1] = __float_as_uint(Elo[kf  ][m+8]);
                Ail[mt][2] = __float_as_uint(Elo[kf+4][m]);
                Ail[mt][3] = __float_as_uint(Elo[kf+4][m+8]);
            }
#pragma unroll
            for (int nt = 0; nt < 4; nt++) {
                int c = wn*32 + nt*8 + lrow;
                uint32_t bh0 = __float_as_uint(Xhi[kf  ][c]);
                uint32_t bh1 = __float_as_uint(Xhi[kf+4][c]);
                uint32_t bl0 = __float_as_uint(Xlo[kf  ][c]);
                uint32_t bl1 = __float_as_uint(Xlo[kf+4][c]);
#pragma unroll
                for (int mt = 0; mt < 2; mt++) {
                    mma8(acc[mt][nt], Aih[mt], bh0, bh1);
                    mma8(acc[mt][nt], Aih[mt], bl0, bl1);
                    mma8(acc[mt][nt], Ail[mt], bh0, bh1);
                }
            }
        }
        __syncthreads();
    }
    // atomic epilogue
#pragma unroll
    for (int mt = 0; mt < 2; mt++) {
#pragma unroll
        for (int nt = 0; nt < 4; nt++) {
            int row0 = wm*32 + mt*16 + lrow;
            int col  = c0 + wn*32 + nt*8 + 2*lcol;
            float* p0 = &spec[((size_t)b*KK + row0    ) * CC + col];
            float* p1 = &spec[((size_t)b*KK + row0 + 8) * CC + col];
            atomicAdd(p0,     acc[mt][nt][0]);
            atomicAdd(p0 + 1, acc[mt][nt][1]);
            atomicAdd(p1,     acc[mt][nt][2]);
            atomicAdd(p1 + 1, acc[mt][nt][3]);
        }
    }
}

// =====================================================================
// generic 3x-tf32 mma GEMM: out[b,r,c] = sum_k A[b,row(r),k]*W[b,k,c] (+bias)
// block tile 128 rows x 64 cols; nW selects among up to 3 W/bias/out sets
// (blockIdx.z = b*nW + sel)
// =====================================================================
__global__ void __launch_bounds__(256) k_gemm_mma(
    const float* __restrict__ A, const int* __restrict__ gidx, long long aBatch,
    const float* __restrict__ W0, const float* __restrict__ W1,
    const float* __restrict__ W2, long long wBatch,
    const float* __restrict__ bias0, const float* __restrict__ bias1,
    const float* __restrict__ bias2,
    float* __restrict__ out0, float* __restrict__ out1, float* __restrict__ out2,
    long long oBatch, int Kd, int nW)
{
    int z   = blockIdx.z;
    int b   = z / nW;
    int sel = z - b * nW;
    int r0  = blockIdx.x * 128;
    int c0  = blockIdx.y * 64;

    const float* W    = (sel == 0) ? W0    : (sel == 1) ? W1    : W2;
    const float* bias = (sel == 0) ? bias0 : (sel == 1) ? bias1 : bias2;
    float*       out  = (sel == 0) ? out0  : (sel == 1) ? out1  : out2;

    __shared__ float Ahi[128][17], Alo[128][17];
    __shared__ float Bhi[16][68],  Blo[16][68];
    int tid  = threadIdx.x;
    int wid  = tid >> 5, lane = tid & 31;
    int wm   = wid & 3;
    int wn   = wid >> 2;
    int lrow = lane >> 2;
    int lcol = lane & 3;

    const float* Ab = A + (size_t)b * aBatch;
    const float* Wb = W + (size_t)b * wBatch;
    float*       Ob = out + (size_t)b * oBatch;

    float acc[2][4][4];
#pragma unroll
    for (int mt = 0; mt < 2; mt++)
#pragma unroll
        for (int nt = 0; nt < 4; nt++)
#pragma unroll
            for (int j = 0; j < 4; j++) acc[mt][nt][j] = 0.f;

    for (int kc = 0; kc < Kd; kc += 16) {
        // load A tile 128 x 16 (hi/lo)
#pragma unroll
        for (int v = tid; v < 512; v += 256) {
            int r = v >> 2, k4 = v & 3;
            int gr = gidx ? gidx[b*MM + r0 + r] : (r0 + r);
            float4 a = *reinterpret_cast<const float4*>(
                Ab + (size_t)gr * Kd + kc + k4*4);
            float h;
            h = tf32r(a.x); Ahi[r][k4*4+0] = h; Alo[r][k4*4+0] = tf32r(a.x - h);
            h = tf32r(a.y); Ahi[r][k4*4+1] = h; Alo[r][k4*4+1] = tf32r(a.y - h);
            h = tf32r(a.z); Ahi[r][k4*4+2] = h; Alo[r][k4*4+2] = tf32r(a.z - h);
            h = tf32r(a.w); Ahi[r][k4*4+3] = h; Alo[r][k4*4+3] = tf32r(a.w - h);
        }
        // load B tile 16 x 64 (hi/lo)
        {
            int r = tid >> 4, c4 = tid & 15;
            float4 wv = *reinterpret_cast<const float4*>(
                Wb + (size_t)(kc + r) * CC + c0 + c4*4);
            float4 h, l;
            h.x = tf32r(wv.x); l.x = tf32r(wv.x - h.x);
            h.y = tf32r(wv.y); l.y = tf32r(wv.y - h.y);
            h.z = tf32r(wv.z); l.z = tf32r(wv.z - h.z);
            h.w = tf32r(wv.w); l.w = tf32r(wv.w - h.w);
            *reinterpret_cast<float4*>(&Bhi[r][c4*4]) = h;
            *reinterpret_cast<float4*>(&Blo[r][c4*4]) = l;
        }
        __syncthreads();
#pragma unroll
        for (int ks = 0; ks < 2; ks++) {
            int kf = ks*8 + lcol;
            uint32_t Aih[2][4], Ail[2][4];
#pragma unroll
            for (int mt = 0; mt < 2; mt++) {
                int m = wm*32 + mt*16 + lrow;
                Aih[mt][0] = __float_as_uint(Ahi[m  ][kf]);
                Aih[mt][1] = __float_as_uint(Ahi[m+8][kf]);
                Aih[mt][2] = __float_as_uint(Ahi[m  ][kf+4]);
                Aih[mt][3] = __float_as_uint(Ahi[m+8][kf+4]);
                Ail[mt][0] = __float_as_uint(Alo[m  ][kf]);
                Ail[mt][1] = __float_as_uint(Alo[m+8][kf]);
                Ail[mt][2] = __float_as_uint(Alo[m  ][kf+4]);
                Ail[mt][3] = __float_as_uint(Alo[m+8][kf+4]);
            }
#pragma unroll
            for (int nt = 0; nt < 4; nt++) {
                int c = wn*32 + nt*8 + lrow;
                uint32_t bh0 = __float_as_uint(Bhi[kf  ][c]);
                uint32_t bh1 = __float_as_uint(Bhi[kf+4][c]);
                uint32_t bl0 = __float_as_uint(Blo[kf  ][c]);
                uint32_t bl1 = __float_as_uint(Blo[kf+4][c]);
#pragma unroll
                for (int mt = 0; mt < 2; mt++) {
                    mma8(acc[mt][nt], Aih[mt], bh0, bh1);
                    mma8(acc[mt][nt], Aih[mt], bl0, bl1);
                    mma8(acc[mt][nt], Ail[mt], bh0, bh1);
                }
            }
        }
        __syncthreads();
    }
    // epilogue
#pragma unroll
    for (int mt = 0; mt < 2; mt++) {
#pragma unroll
        for (int nt = 0; nt < 4; nt++) {
            int row0 = r0 + wm*32 + mt*16 + lrow;
            int col  = c0 + wn*32 + nt*8 + 2*lcol;
            float b0v = bias ? bias[col]     : 0.f;
            float b1v = bias ? bias[col + 1] : 0.f;
            float2 v0 = {acc[mt][nt][0] + b0v, acc[mt][nt][1] + b1v};
            float2 v1 = {acc[mt][nt][2] + b0v, acc[mt][nt][3] + b1v};
            *reinterpret_cast<float2*>(&Ob[(size_t)row0       * CC + col]) = v0;
            *reinterpret_cast<float2*>(&Ob[(size_t)(row0 + 8) * CC + col]) = v1;
        }
    }
}

// ---------------- spectral coefficient multiply (+ optional out_w fold) ----------------
__global__ void k_coef(const float* __restrict__ evals, const float* __restrict__ tvec,
                       const float* __restrict__ specin, float* __restrict__ specout,
                       const float* __restrict__ outw)
{
    int bk = blockIdx.x;             // b*K + k
    int b = bk >> 7, k = bk & 127;
    int c = threadIdx.x;
    float t = fmaxf(tvec[c], 1e-8f);
    float w = outw ? fmaxf(outw[c], 1e-8f) : 1.f;
    specout[(size_t)bk*CC + c] = expf(-evals[b*KK + k] * t) * specin[(size_t)bk*CC + c] * w;
}

// ---------------- GroupNorm stats ----------------
__global__ void k_gnstats()
{
    int b = blockIdx.x >> 5, g = blockIdx.x & 31;
    int tid = threadIdx.x;
    float s = 0.f, s2 = 0.f;
    for (int e = tid; e < MM*8; e += 256) {
        int m = e >> 3, j = e & 7;
        float v = g_xfar[((size_t)(b*MM + m)) * CC + (g << 3) + j];
        s += v; s2 += v * v;
    }
    __shared__ float rs[256], rq[256];
    rs[tid] = s; rq[tid] = s2;
    __syncthreads();
    for (int o = 128; o > 0; o >>= 1) {
        if (tid < o) { rs[tid] += rs[tid+o]; rq[tid] += rq[tid+o]; }
        __syncthreads();
    }
    if (tid == 0) {
        float mean = rs[0] * (1.f/8192.f);
        float var  = rq[0] * (1.f/8192.f) - mean*mean;
        g_gnm[blockIdx.x] = mean;
        g_gnr[blockIdx.x] = rsqrtf(var + 1e-6f);
    }
}

// ---------------- GroupNorm apply (in place) ----------------
__global__ void k_gnapply(const float* __restrict__ gn_w, const float* __restrict__ gn_b)
{
    int i = blockIdx.x * blockDim.x + threadIdx.x;
    int base = i * 4;
    int c  = base & 255;
    int bm = base >> 8;
    int b  = bm >> 10;
    int g  = c >> 3;
    float mean = g_gnm[b*GG + g];
    float r    = g_gnr[b*GG + g];
    float4 v = *reinterpret_cast<float4*>(&g_xfar[base]);
    v.x = (v.x - mean) * r * gn_w[c+0] + gn_b[c+0];
    v.y = (v.y - mean) * r * gn_w[c+1] + gn_b[c+1];
    v.z = (v.z - mean) * r * gn_w[c+2] + gn_b[c+2];
    v.w = (v.w - mean) * r * gn_w[c+3] + gn_b[c+3];
    *reinterpret_cast<float4*>(&g_xfar[base]) = v;
}

// ---------------- flash attention: 64-query tiles, online softmax ----------------
__global__ void k_attn()
{
    int b = blockIdx.z, h = blockIdx.y, q0 = blockIdx.x * 64;
    __shared__ float Qs[64][32];
    __shared__ float Ks[64][32];
    __shared__ float Vs[64][32];
    __shared__ float Ps[64][65];
    __shared__ float redm[4][64];
    __shared__ float redl[4][64];
    int tid = threadIdx.x;
    int q  = tid & 63;
    int cg = tid >> 6;   // 0..3

    for (int v = tid; v < 512; v += 256) {
        int r = v >> 3, d4 = v & 7;
        reinterpret_cast<float4*>(&Qs[r][0])[d4] =
            *reinterpret_cast<const float4*>(&g_q[((size_t)(b*MM) + q0 + r) * CC + h*DD + d4*4]);
    }
    __syncthreads();
    float qreg[32];
#pragma unroll
    for (int d = 0; d < 32; d += 4) {
        float4 t = *reinterpret_cast<float4*>(&Qs[q][d]);
        qreg[d] = t.x; qreg[d+1] = t.y; qreg[d+2] = t.z; qreg[d+3] = t.w;
    }
    float orun[8];
#pragma unroll
    for (int j = 0; j < 8; j++) orun[j] = 0.f;
    float mrun = -1e30f, lrun = 0.f;
    const float scale = 0.17677669529663687f;

    for (int kt = 0; kt < 16; kt++) {
        __syncthreads();
        for (int v = tid; v < 512; v += 256) {
            int r = v >> 3, d4 = v & 7;
            size_t gi = ((size_t)b*MM + kt*64 + r) * CC + h*DD + d4*4;
            reinterpret_cast<float4*>(&Ks[r][0])[d4] =
                *reinterpret_cast<const float4*>(&g_kmat[gi]);
            reinterpret_cast<float4*>(&Vs[r][0])[d4] =
                *reinterpret_cast<const float4*>(&g_v[gi]);
        }
        __syncthreads();

        float s[16];
        float lm = -1e30f;
#pragma unroll
        for (int kk = 0; kk < 16; kk++) {
            int ki = cg*16 + kk;
            float a = 0.f;
#pragma unroll
            for (int d4 = 0; d4 < 8; d4++) {
                float4 k4 = *reinterpret_cast<float4*>(&Ks[ki][d4*4]);
                a += qreg[d4*4+0]*k4.x + qreg[d4*4+1]*k4.y
                   + qreg[d4*4+2]*k4.z + qreg[d4*4+3]*k4.w;
            }
            s[kk] = a * scale;
            lm = fmaxf(lm, s[kk]);
        }
        redm[cg][q] = lm;
        __syncthreads();
        float mt = fmaxf(fmaxf(redm[0][q], redm[1][q]), fmaxf(redm[2][q], redm[3][q]));
        float mnew = fmaxf(mrun, mt);
        float lsum = 0.f;
#pragma unroll
        for (int kk = 0; kk < 16; kk++) { s[kk] = expf(s[kk] - mnew); lsum += s[kk]; }
        redl[cg][q] = lsum;
#pragma unroll
        for (int kk = 0; kk < 16; kk++) Ps[q][cg*16 + kk] = s[kk];
        __syncthreads();
        float ltile = redl[0][q] + redl[1][q] + redl[2][q] + redl[3][q];
        float corr  = expf(mrun - mnew);
        lrun = lrun * corr + ltile;
#pragma unroll
        for (int j = 0; j < 8; j++) orun[j] *= corr;
#pragma unroll
        for (int k2 = 0; k2 < 64; k2++) {
            float p = Ps[q][k2];
            float4 v0 = *reinterpret_cast<float4*>(&Vs[k2][cg*8]);
            float4 v1 = *reinterpret_cast<float4*>(&Vs[k2][cg*8 + 4]);
            orun[0] += p*v0.x; orun[1] += p*v0.y; orun[2] += p*v0.z; orun[3] += p*v0.w;
            orun[4] += p*v1.x; orun[5] += p*v1.y; orun[6] += p*v1.z; orun[7] += p*v1.w;
        }
        mrun = mnew;
    }
    float inv = 1.f / lrun;
    size_t o = ((size_t)(b*MM) + q0 + q) * CC + h*DD + cg*8;
    float4 w0 = {orun[0]*inv, orun[1]*inv, orun[2]*inv, orun[3]*inv};
    float4 w1 = {orun[4]*inv, orun[5]*inv, orun[6]*inv, orun[7]*inv};
    *reinterpret_cast<float4*>(&g_ao[o])     = w0;
    *reinterpret_cast<float4*>(&g_ao[o + 4]) = w1;
}

// ---------------- launch ----------------
extern "C" void kernel_launch(void* const* d_in, const int* in_sizes, int n_in,
                              void* d_out, int out_size)
{
    const float* x       = (const float*)d_in[0];
    const float* mass    = (const float*)d_in[1];
    const float* evals   = (const float*)d_in[2];
    const float* evecs   = (const float*)d_in[3];
    const int*   far_idx = (const int*)  d_in[4];
    const float* t_in    = (const float*)d_in[5];
    const float* t_out   = (const float*)d_in[6];
    const float* gn_w    = (const float*)d_in[7];
    const float* gn_b    = (const float*)d_in[8];
    const float* Wq      = (const float*)d_in[9];
    const float* bq      = (const float*)d_in[10];
    const float* Wk      = (const float*)d_in[11];
    const float* bk      = (const float*)d_in[12];
    const float* Wv      = (const float*)d_in[13];
    const float* bv      = (const float*)d_in[14];
    const float* Wo      = (const float*)d_in[15];
    const float* bo      = (const float*)d_in[16];
    const float* out_w   = (const float*)d_in[17];
    float* out = (float*)d_out;

    float *p_spec1, *p_spec1m, *p_spec2, *p_spec2m, *p_xfar, *p_q, *p_k, *p_v, *p_ao, *p_proj;
    cudaGetSymbolAddress((void**)&p_spec1,  g_spec1);
    cudaGetSymbolAddress((void**)&p_spec1m, g_spec1m);
    cudaGetSymbolAddress((void**)&p_spec2,  g_spec2);
    cudaGetSymbolAddress((void**)&p_spec2m, g_spec2m);
    cudaGetSymbolAddress((void**)&p_xfar,   g_xfar);
    cudaGetSymbolAddress((void**)&p_q,      g_q);
    cudaGetSymbolAddress((void**)&p_k,      g_kmat);
    cudaGetSymbolAddress((void**)&p_v,      g_v);
    cudaGetSymbolAddress((void**)&p_ao,     g_ao);
    cudaGetSymbolAddress((void**)&p_proj,   g_proj);

    const long long AKC = (long long)KK * CC;
    const long long AMC = (long long)MM * CC;
    const long long ANK = (long long)NN * KK;
    const long long ANC = (long long)NN * CC;

    k_zero<<<512, 256>>>();

    // to_basis 1: full N, split-K over 16 chunks of 2048 (3x tf32 mma)
    k_tobasis_mma<<<dim3(16, 4, BB), 256>>>(x, mass, evecs, nullptr, p_spec1, 2048, NN);
    k_coef<<<BB*KK, CC>>>(evals, t_in, p_spec1, p_spec1m, nullptr);

    // from_basis 1: only the M gathered rows (3x tf32 mma)
    k_gemm_mma<<<dim3(MM/128, 4, BB), 256>>>(
        evecs, far_idx, ANK,
        p_spec1m, nullptr, nullptr, AKC,
        nullptr, nullptr, nullptr,
        p_xfar, nullptr, nullptr, AMC, KK, 1);

    // GroupNorm
    k_gnstats<<<BB*GG, 256>>>();
    k_gnapply<<<(BB*MM*CC/4)/256, 256>>>(gn_w, gn_b);

    // QKV projections fused (nW=3)
    k_gemm_mma<<<dim3(MM/128, 4, BB*3), 256>>>(
        p_xfar, nullptr, AMC,
        Wq, Wk, Wv, 0,
        bq, bk, bv,
        p_q, p_k, p_v, AMC, CC, 3);

    // attention
    k_attn<<<dim3(MM/64, HH, BB), 256>>>();

    // output projection
    k_gemm_mma<<<dim3(MM/128, 4, BB), 256>>>(
        p_ao, nullptr, AMC,
        Wo, nullptr, nullptr, 0,
        bo, nullptr, nullptr,
        p_proj, nullptr, nullptr, AMC, CC, 1);

    // to_basis 2: only the M scattered rows (3x tf32 mma)
    k_tobasis_mma<<<dim3(4, 4, BB), 256>>>(p_proj, mass, evecs, far_idx, p_spec2, 256, MM);
    k_coef<<<BB*KK, CC>>>(evals, t_out, p_spec2, p_spec2m, out_w);

    // from_basis 2: full N output (out_w folded into spec2m)
    k_gemm_mma<<<dim3(NN/128, 4, BB), 256>>>(
        evecs, nullptr, ANK,
        p_spec2m, nullptr, nullptr, AKC,
        nullptr, nullptr, nullptr,
        out, nullptr, nullptr, ANC, KK, 1);
}

// round 5
// speedup vs baseline: 1.3692x; 1.1419x over previous
#include <cuda_runtime.h>
#include <math.h>
#include <stdint.h>

#define BB 4
#define NN 32768
#define KK 128
#define MM 1024
#define CC 256
#define GG 32
#define HH 8
#define DD 32

// ---------------- scratch (device globals; no allocation allowed) ----------------
__device__ float g_spec1 [BB*KK*CC];
__device__ float g_spec1m[BB*KK*CC];
__device__ float g_spec2 [BB*KK*CC];
__device__ float g_spec2m[BB*KK*CC];
__device__ float g_xfar  [BB*MM*CC];
__device__ float g_q     [BB*MM*CC];
__device__ float g_kmat  [BB*MM*CC];
__device__ float g_v     [BB*MM*CC];
__device__ float g_ao    [BB*MM*CC];
__device__ float g_proj  [BB*MM*CC];
__device__ float g_gnm   [BB*GG];
__device__ float g_gnr   [BB*GG];

// ---------------- tf32 helpers ----------------
__device__ __forceinline__ float tf32r(float x) {
    uint32_t u; asm("cvt.rna.tf32.f32 %0, %1;" : "=r"(u) : "f"(x));
    return __uint_as_float(u);
}

__device__ __forceinline__ void mma8(float d[4], const uint32_t a[4],
                                     uint32_t b0, uint32_t b1) {
    asm volatile(
        "mma.sync.aligned.m16n8k8.row.col.f32.tf32.tf32.f32 "
        "{%0,%1,%2,%3},{%4,%5,%6,%7},{%8,%9},{%0,%1,%2,%3};\n"
        : "+f"(d[0]), "+f"(d[1]), "+f"(d[2]), "+f"(d[3])
        : "r"(a[0]), "r"(a[1]), "r"(a[2]), "r"(a[3]), "r"(b0), "r"(b1));
}

// ---------------- zero the atomic accumulators ----------------
__global__ void k_zero() {
    int i = blockIdx.x * blockDim.x + threadIdx.x;
    if (i < BB*KK*CC) { g_spec1[i] = 0.f; g_spec2[i] = 0.f; }
}

// =====================================================================
// to_basis via 3x-tf32 mma, double-buffered + reg-prefetch pipeline.
// spec[b,k,c] += sum_n E[b,row(n),k]*mass*X[b,n,c]
// block: 128 (k_spec) x 64 (c); split-K over N chunks, atomicAdd epilogue.
// dynamic smem: Ehi/Elo [2][16][132], Xhi/Xlo [2][16][68]
// =====================================================================
#define TOB_SMEM_FLOATS (2*16*132*2 + 2*16*68*2)   // 12800 floats = 51200 B

__global__ void __launch_bounds__(256,2) k_tobasis_mma(
    const float* __restrict__ X, const float* __restrict__ mass,
    const float* __restrict__ evecs, const int* __restrict__ gidx,
    float* __restrict__ spec, int chunk, int xRowsPerBatch)
{
    extern __shared__ float sm[];
    float* sEhi = sm;                 // [2][16][132]
    float* sElo = sEhi + 2*16*132;
    float* sXhi = sElo + 2*16*132;    // [2][16][68]
    float* sXlo = sXhi + 2*16*68;
#define EHI(bf,r,c) sEhi[(bf)*2112 + (r)*132 + (c)]
#define ELO(bf,r,c) sElo[(bf)*2112 + (r)*132 + (c)]
#define XHI(bf,r,c) sXhi[(bf)*1088 + (r)*68 + (c)]
#define XLO(bf,r,c) sXlo[(bf)*1088 + (r)*68 + (c)]

    int b  = blockIdx.z;
    int c0 = blockIdx.y * 64;
    int n0 = blockIdx.x * chunk;
    int tid  = threadIdx.x;
    int wid  = tid >> 5, lane = tid & 31;
    int wm   = wid & 3;          // 4 warps over k_spec (32 each)
    int wn   = wid >> 2;         // 2 warps over c (32 each)
    int lrow = lane >> 2;        // 0..7
    int lcol = lane & 3;         // 0..3

    int iters = chunk >> 4;

    // per-thread fetch slots: E rows at v=tid and v=tid+256; X row at tid>>4
    int er0 = tid >> 5,         ec0 = tid & 31;
    int er1 = (tid + 256) >> 5, ec1 = (tid + 256) & 31;
    int xr  = tid >> 4,         xc  = tid & 15;

    float4 pe0, pe1, px; float pm;
    float4 qe0, qe1, qx; float qm;

#define TOB_FETCH(it, e0, e1, xv, ms) {                                        \
        int nb = (it) << 4;                                                    \
        int n = n0 + nb + er0;                                                 \
        int rr = gidx ? gidx[b*MM + n] : n;                                    \
        e0 = *reinterpret_cast<const float4*>(&evecs[((size_t)b*NN + rr)*KK + ec0*4]); \
        n = n0 + nb + er1;                                                     \
        rr = gidx ? gidx[b*MM + n] : n;                                        \
        e1 = *reinterpret_cast<const float4*>(&evecs[((size_t)b*NN + rr)*KK + ec1*4]); \
        n = n0 + nb + xr;                                                      \
        rr = gidx ? gidx[b*MM + n] : n;                                        \
        ms = mass[(size_t)b*NN + rr];                                          \
        xv = *reinterpret_cast<const float4*>(&X[((size_t)b*xRowsPerBatch + n)*CC + c0 + xc*4]); \
    }

#define TOB_STS(bf, e0, e1, xv, ms) {                                          \
        float4 h, l;                                                           \
        h.x = tf32r(e0.x); l.x = tf32r(e0.x - h.x);                            \
        h.y = tf32r(e0.y); l.y = tf32r(e0.y - h.y);                            \
        h.z = tf32r(e0.z); l.z = tf32r(e0.z - h.z);                            \
        h.w = tf32r(e0.w); l.w = tf32r(e0.w - h.w);                            \
        *reinterpret_cast<float4*>(&EHI(bf, er0, ec0*4)) = h;                  \
        *reinterpret_cast<float4*>(&ELO(bf, er0, ec0*4)) = l;                  \
        h.x = tf32r(e1.x); l.x = tf32r(e1.x - h.x);                            \
        h.y = tf32r(e1.y); l.y = tf32r(e1.y - h.y);                            \
        h.z = tf32r(e1.z); l.z = tf32r(e1.z - h.z);                            \
        h.w = tf32r(e1.w); l.w = tf32r(e1.w - h.w);                            \
        *reinterpret_cast<float4*>(&EHI(bf, er1, ec1*4)) = h;                  \
        *reinterpret_cast<float4*>(&ELO(bf, er1, ec1*4)) = l;                  \
        float4 xs = xv;                                                        \
        xs.x *= ms; xs.y *= ms; xs.z *= ms; xs.w *= ms;                        \
        h.x = tf32r(xs.x); l.x = tf32r(xs.x - h.x);                            \
        h.y = tf32r(xs.y); l.y = tf32r(xs.y - h.y);                            \
        h.z = tf32r(xs.z); l.z = tf32r(xs.z - h.z);                            \
        h.w = tf32r(xs.w); l.w = tf32r(xs.w - h.w);                            \
        *reinterpret_cast<float4*>(&XHI(bf, xr, xc*4)) = h;                    \
        *reinterpret_cast<float4*>(&XLO(bf, xr, xc*4)) = l;                    \
    }

    float acc[2][4][4];
#pragma unroll
    for (int mt = 0; mt < 2; mt++)
#pragma unroll
        for (int nt = 0; nt < 4; nt++)
#pragma unroll
            for (int j = 0; j < 4; j++) acc[mt][nt][j] = 0.f;

    // prologue
    TOB_FETCH(0, pe0, pe1, px, pm);
    TOB_STS(0, pe0, pe1, px, pm);
    if (iters > 1) TOB_FETCH(1, pe0, pe1, px, pm);
    __syncthreads();

    for (int i = 0; i < iters; i++) {
        int cur = i & 1;
        if (i + 2 < iters) TOB_FETCH(i + 2, qe0, qe1, qx, qm);
        if (i + 1 < iters) TOB_STS(cur ^ 1, pe0, pe1, px, pm);

#pragma unroll
        for (int ks = 0; ks < 2; ks++) {
            int kf = ks*8 + lcol;
            uint32_t Aih[2][4], Ail[2][4];
#pragma unroll
            for (int mt = 0; mt < 2; mt++) {
                int m = wm*32 + mt*16 + lrow;
                Aih[mt][0] = __float_as_uint(EHI(cur, kf,   m));
                Aih[mt][1] = __float_as_uint(EHI(cur, kf,   m+8));
                Aih[mt][2] = __float_as_uint(EHI(cur, kf+4, m));
                Aih[mt][3] = __float_as_uint(EHI(cur, kf+4, m+8));
                Ail[mt][0] = __float_as_uint(ELO(cur, kf,   m));
                Ail[mt][1] = __float_as_uint(ELO(cur, kf,   m+8));
                Ail[mt][2] = __float_as_uint(ELO(cur, kf+4, m));
                Ail[mt][3] = __float_as_uint(ELO(cur, kf+4, m+8));
            }
#pragma unroll
            for (int nt = 0; nt < 4; nt++) {
                int c = wn*32 + nt*8 + lrow;
                uint32_t bh0 = __float_as_uint(XHI(cur, kf,   c));
                uint32_t bh1 = __float_as_uint(XHI(cur, kf+4, c));
                uint32_t bl0 = __float_as_uint(XLO(cur, kf,   c));
                uint32_t bl1 = __float_as_uint(XLO(cur, kf+4, c));
#pragma unroll
                for (int mt = 0; mt < 2; mt++) {
                    mma8(acc[mt][nt], Aih[mt], bh0, bh1);
                    mma8(acc[mt][nt], Aih[mt], bl0, bl1);
                    mma8(acc[mt][nt], Ail[mt], bh0, bh1);
                }
            }
        }
        __syncthreads();
        pe0 = qe0; pe1 = qe1; px = qx; pm = qm;
    }

    // atomic epilogue
#pragma unroll
    for (int mt = 0; mt < 2; mt++) {
#pragma unroll
        for (int nt = 0; nt < 4; nt++) {
            int row0 = wm*32 + mt*16 + lrow;
            int col  = c0 + wn*32 + nt*8 + 2*lcol;
            float* p0 = &spec[((size_t)b*KK + row0    ) * CC + col];
            float* p1 = &spec[((size_t)b*KK + row0 + 8) * CC + col];
            atomicAdd(p0,     acc[mt][nt][0]);
            atomicAdd(p0 + 1, acc[mt][nt][1]);
            atomicAdd(p1,     acc[mt][nt][2]);
            atomicAdd(p1 + 1, acc[mt][nt][3]);
        }
    }
}

// =====================================================================
// generic 3x-tf32 mma GEMM, double-buffered + reg-prefetch pipeline.
// out[b,r,c] = sum_k A[b,row(r),k]*W[b,k,c] (+bias)
// block tile 128 rows x 64 cols; nW selects among up to 3 W/bias/out sets
// dynamic smem: Ahi/Alo [2][128][17], Bhi/Blo [2][16][68]
// =====================================================================
#define GEMM_SMEM_FLOATS (2*128*17*2 + 2*16*68*2)   // 13056 floats = 52224 B

__global__ void __launch_bounds__(256,2) k_gemm_mma(
    const float* __restrict__ A, const int* __restrict__ gidx, long long aBatch,
    const float* __restrict__ W0, const float* __restrict__ W1,
    const float* __restrict__ W2, long long wBatch,
    const float* __restrict__ bias0, const float* __restrict__ bias1,
    const float* __restrict__ bias2,
    float* __restrict__ out0, float* __restrict__ out1, float* __restrict__ out2,
    long long oBatch, int Kd, int nW)
{
    extern __shared__ float sm[];
    float* sAhi = sm;                  // [2][128][17]
    float* sAlo = sAhi + 2*128*17;
    float* sBhi = sAlo + 2*128*17;     // [2][16][68]
    float* sBlo = sBhi + 2*16*68;
#define AHI(bf,r,k) sAhi[(bf)*2176 + (r)*17 + (k)]
#define ALO(bf,r,k) sAlo[(bf)*2176 + (r)*17 + (k)]
#define BHI(bf,r,c) sBhi[(bf)*1088 + (r)*68 + (c)]
#define BLO(bf,r,c) sBlo[(bf)*1088 + (r)*68 + (c)]

    int z   = blockIdx.z;
    int b   = z / nW;
    int sel = z - b * nW;
    int r0  = blockIdx.x * 128;
    int c0  = blockIdx.y * 64;

    const float* W    = (sel == 0) ? W0    : (sel == 1) ? W1    : W2;
    const float* bias = (sel == 0) ? bias0 : (sel == 1) ? bias1 : bias2;
    float*       out  = (sel == 0) ? out0  : (sel == 1) ? out1  : out2;

    int tid  = threadIdx.x;
    int wid  = tid >> 5, lane = tid & 31;
    int wm   = wid & 3;
    int wn   = wid >> 2;
    int lrow = lane >> 2;
    int lcol = lane & 3;

    const float* Ab = A + (size_t)b * aBatch;
    const float* Wb = W + (size_t)b * wBatch;
    float*       Ob = out + (size_t)b * oBatch;

    int iters = Kd >> 4;

    int ar0 = tid >> 2,         ak0 = tid & 3;
    int ar1 = (tid + 256) >> 2, ak1 = (tid + 256) & 3;
    int br  = tid >> 4,         bc  = tid & 15;
    int ga0 = gidx ? gidx[b*MM + r0 + ar0] : (r0 + ar0);
    int ga1 = gidx ? gidx[b*MM + r0 + ar1] : (r0 + ar1);

    float4 pa0, pa1, pw;
    float4 qa0, qa1, qw;

#define G_FETCH(it, a0, a1, wv) {                                              \
        int kc = (it) << 4;                                                    \
        a0 = *reinterpret_cast<const float4*>(Ab + (size_t)ga0 * Kd + kc + ak0*4); \
        a1 = *reinterpret_cast<const float4*>(Ab + (size_t)ga1 * Kd + kc + ak1*4); \
        wv = *reinterpret_cast<const float4*>(Wb + (size_t)(kc + br) * CC + c0 + bc*4); \
    }

#define G_STS(bf, a0, a1, wv) {                                                \
        float h;                                                               \
        h = tf32r(a0.x); AHI(bf,ar0,ak0*4+0)=h; ALO(bf,ar0,ak0*4+0)=tf32r(a0.x-h); \
        h = tf32r(a0.y); AHI(bf,ar0,ak0*4+1)=h; ALO(bf,ar0,ak0*4+1)=tf32r(a0.y-h); \
        h = tf32r(a0.z); AHI(bf,ar0,ak0*4+2)=h; ALO(bf,ar0,ak0*4+2)=tf32r(a0.z-h); \
        h = tf32r(a0.w); AHI(bf,ar0,ak0*4+3)=h; ALO(bf,ar0,ak0*4+3)=tf32r(a0.w-h); \
        h = tf32r(a1.x); AHI(bf,ar1,ak1*4+0)=h; ALO(bf,ar1,ak1*4+0)=tf32r(a1.x-h); \
        h = tf32r(a1.y); AHI(bf,ar1,ak1*4+1)=h; ALO(bf,ar1,ak1*4+1)=tf32r(a1.y-h); \
        h = tf32r(a1.z); AHI(bf,ar1,ak1*4+2)=h; ALO(bf,ar1,ak1*4+2)=tf32r(a1.z-h); \
        h = tf32r(a1.w); AHI(bf,ar1,ak1*4+3)=h; ALO(bf,ar1,ak1*4+3)=tf32r(a1.w-h); \
        float4 hh, ll;                                                         \
        hh.x = tf32r(wv.x); ll.x = tf32r(wv.x - hh.x);                         \
        hh.y = tf32r(wv.y); ll.y = tf32r(wv.y - hh.y);                         \
        hh.z = tf32r(wv.z); ll.z = tf32r(wv.z - hh.z);                         \
        hh.w = tf32r(wv.w); ll.w = tf32r(wv.w - hh.w);                         \
        *reinterpret_cast<float4*>(&BHI(bf, br, bc*4)) = hh;                   \
        *reinterpret_cast<float4*>(&BLO(bf, br, bc*4)) = ll;                   \
    }

    float acc[2][4][4];
#pragma unroll
    for (int mt = 0; mt < 2; mt++)
#pragma unroll
        for (int nt = 0; nt < 4; nt++)
#pragma unroll
            for (int j = 0; j < 4; j++) acc[mt][nt][j] = 0.f;

    // prologue
    G_FETCH(0, pa0, pa1, pw);
    G_STS(0, pa0, pa1, pw);
    if (iters > 1) G_FETCH(1, pa0, pa1, pw);
    __syncthreads();

    for (int i = 0; i < iters; i++) {
        int cur = i & 1;
        if (i + 2 < iters) G_FETCH(i + 2, qa0, qa1, qw);
        if (i + 1 < iters) G_STS(cur ^ 1, pa0, pa1, pw);

#pragma unroll
        for (int ks = 0; ks < 2; ks++) {
            int kf = ks*8 + lcol;
            uint32_t Aih[2][4], Ail[2][4];
#pragma unroll
            for (int mt = 0; mt < 2; mt++) {
                int m = wm*32 + mt*16 + lrow;
                Aih[mt][0] = __float_as_uint(AHI(cur, m,   kf));
                Aih[mt][1] = __float_as_uint(AHI(cur, m+8, kf));
                Aih[mt][2] = __float_as_uint(AHI(cur, m,   kf+4));
                Aih[mt][3] = __float_as_uint(AHI(cur, m+8, kf+4));
                Ail[mt][0] = __float_as_uint(ALO(cur, m,   kf));
                Ail[mt][1] = __float_as_uint(ALO(cur, m+8, kf));
                Ail[mt][2] = __float_as_uint(ALO(cur, m,   kf+4));
                Ail[mt][3] = __float_as_uint(ALO(cur, m+8, kf+4));
            }
#pragma unroll
            for (int nt = 0; nt < 4; nt++) {
                int c = wn*32 + nt*8 + lrow;
                uint32_t bh0 = __float_as_uint(BHI(cur, kf,   c));
                uint32_t bh1 = __float_as_uint(BHI(cur, kf+4, c));
                uint32_t bl0 = __float_as_uint(BLO(cur, kf,   c));
                uint32_t bl1 = __float_as_uint(BLO(cur, kf+4, c));
#pragma unroll
                for (int mt = 0; mt < 2; mt++) {
                    mma8(acc[mt][nt], Aih[mt], bh0, bh1);
                    mma8(acc[mt][nt], Aih[mt], bl0, bl1);
                    mma8(acc[mt][nt], Ail[mt], bh0, bh1);
                }
            }
        }
        __syncthreads();
        pa0 = qa0; pa1 = qa1; pw = qw;
    }

    // epilogue
#pragma unroll
    for (int mt = 0; mt < 2; mt++) {
#pragma unroll
        for (int nt = 0; nt < 4; nt++) {
            int row0 = r0 + wm*32 + mt*16 + lrow;
            int col  = c0 + wn*32 + nt*8 + 2*lcol;
            float b0v = bias ? bias[col]     : 0.f;
            float b1v = bias ? bias[col + 1] : 0.f;
            float2 v0 = {acc[mt][nt][0] + b0v, acc[mt][nt][1] + b1v};
            float2 v1 = {acc[mt][nt][2] + b0v, acc[mt][nt][3] + b1v};
            *reinterpret_cast<float2*>(&Ob[(size_t)row0       * CC + col]) = v0;
            *reinterpret_cast<float2*>(&Ob[(size_t)(row0 + 8) * CC + col]) = v1;
        }
    }
}

// ---------------- spectral coefficient multiply (+ optional out_w fold) ----------------
__global__ void k_coef(const float* __restrict__ evals, const float* __restrict__ tvec,
                       const float* __restrict__ specin, float* __restrict__ specout,
                       const float* __restrict__ outw)
{
    int bk = blockIdx.x;             // b*K + k
    int b = bk >> 7, k = bk & 127;
    int c = threadIdx.x;
    float t = fmaxf(tvec[c], 1e-8f);
    float w = outw ? fmaxf(outw[c], 1e-8f) : 1.f;
    specout[(size_t)bk*CC + c] = expf(-evals[b*KK + k] * t) * specin[(size_t)bk*CC + c] * w;
}

// ---------------- GroupNorm stats ----------------
__global__ void k_gnstats()
{
    int b = blockIdx.x >> 5, g = blockIdx.x & 31;
    int tid = threadIdx.x;
    float s = 0.f, s2 = 0.f;
    for (int e = tid; e < MM*8; e += 256) {
        int m = e >> 3, j = e & 7;
        float v = g_xfar[((size_t)(b*MM + m)) * CC + (g << 3) + j];
        s += v; s2 += v * v;
    }
    __shared__ float rs[256], rq[256];
    rs[tid] = s; rq[tid] = s2;
    __syncthreads();
    for (int o = 128; o > 0; o >>= 1) {
        if (tid < o) { rs[tid] += rs[tid+o]; rq[tid] += rq[tid+o]; }
        __syncthreads();
    }
    if (tid == 0) {
        float mean = rs[0] * (1.f/8192.f);
        float var  = rq[0] * (1.f/8192.f) - mean*mean;
        g_gnm[blockIdx.x] = mean;
        g_gnr[blockIdx.x] = rsqrtf(var + 1e-6f);
    }
}

// ---------------- GroupNorm apply (in place) ----------------
__global__ void k_gnapply(const float* __restrict__ gn_w, const float* __restrict__ gn_b)
{
    int i = blockIdx.x * blockDim.x + threadIdx.x;
    int base = i * 4;
    int c  = base & 255;
    int bm = base >> 8;
    int b  = bm >> 10;
    int g  = c >> 3;
    float mean = g_gnm[b*GG + g];
    float r    = g_gnr[b*GG + g];
    float4 v = *reinterpret_cast<float4*>(&g_xfar[base]);
    v.x = (v.x - mean) * r * gn_w[c+0] + gn_b[c+0];
    v.y = (v.y - mean) * r * gn_w[c+1] + gn_b[c+1];
    v.z = (v.z - mean) * r * gn_w[c+2] + gn_b[c+2];
    v.w = (v.w - mean) * r * gn_w[c+3] + gn_b[c+3];
    *reinterpret_cast<float4*>(&g_xfar[base]) = v;
}

// ---------------- flash attention: 64-query tiles, online softmax ----------------
__global__ void k_attn()
{
    int b = blockIdx.z, h = blockIdx.y, q0 = blockIdx.x * 64;
    __shared__ float Qs[64][32];
    __shared__ float Ks[64][32];
    __shared__ float Vs[64][32];
    __shared__ float Ps[64][65];
    __shared__ float redm[4][64];
    __shared__ float redl[4][64];
    int tid = threadIdx.x;
    int q  = tid & 63;
    int cg = tid >> 6;   // 0..3

    for (int v = tid; v < 512; v += 256) {
        int r = v >> 3, d4 = v & 7;
        reinterpret_cast<float4*>(&Qs[r][0])[d4] =
            *reinterpret_cast<const float4*>(&g_q[((size_t)(b*MM) + q0 + r) * CC + h*DD + d4*4]);
    }
    __syncthreads();
    float qreg[32];
#pragma unroll
    for (int d = 0; d < 32; d += 4) {
        float4 t = *reinterpret_cast<float4*>(&Qs[q][d]);
        qreg[d] = t.x; qreg[d+1] = t.y; qreg[d+2] = t.z; qreg[d+3] = t.w;
    }
    float orun[8];
#pragma unroll
    for (int j = 0; j < 8; j++) orun[j] = 0.f;
    float mrun = -1e30f, lrun = 0.f;
    const float scale = 0.17677669529663687f;

    for (int kt = 0; kt < 16; kt++) {
        __syncthreads();
        for (int v = tid; v < 512; v += 256) {
            int r = v >> 3, d4 = v & 7;
            size_t gi = ((size_t)b*MM + kt*64 + r) * CC + h*DD + d4*4;
            reinterpret_cast<float4*>(&Ks[r][0])[d4] =
                *reinterpret_cast<const float4*>(&g_kmat[gi]);
            reinterpret_cast<float4*>(&Vs[r][0])[d4] =
                *reinterpret_cast<const float4*>(&g_v[gi]);
        }
        __syncthreads();

        float s[16];
        float lm = -1e30f;
#pragma unroll
        for (int kk = 0; kk < 16; kk++) {
            int ki = cg*16 + kk;
            float a = 0.f;
#pragma unroll
            for (int d4 = 0; d4 < 8; d4++) {
                float4 k4 = *reinterpret_cast<float4*>(&Ks[ki][d4*4]);
                a += qreg[d4*4+0]*k4.x + qreg[d4*4+1]*k4.y
                   + qreg[d4*4+2]*k4.z + qreg[d4*4+3]*k4.w;
            }
            s[kk] = a * scale;
            lm = fmaxf(lm, s[kk]);
        }
        redm[cg][q] = lm;
        __syncthreads();
        float mt = fmaxf(fmaxf(redm[0][q], redm[1][q]), fmaxf(redm[2][q], redm[3][q]));
        float mnew = fmaxf(mrun, mt);
        float lsum = 0.f;
#pragma unroll
        for (int kk = 0; kk < 16; kk++) { s[kk] = expf(s[kk] - mnew); lsum += s[kk]; }
        redl[cg][q] = lsum;
#pragma unroll
        for (int kk = 0; kk < 16; kk++) Ps[q][cg*16 + kk] = s[kk];
        __syncthreads();
        float ltile = redl[0][q] + redl[1][q] + redl[2][q] + redl[3][q];
        float corr  = expf(mrun - mnew);
        lrun = lrun * corr + ltile;
#pragma unroll
        for (int j = 0; j < 8; j++) orun[j] *= corr;
#pragma unroll
        for (int k2 = 0; k2 < 64; k2++) {
            float p = Ps[q][k2];
            float4 v0 = *reinterpret_cast<float4*>(&Vs[k2][cg*8]);
            float4 v1 = *reinterpret_cast<float4*>(&Vs[k2][cg*8 + 4]);
            orun[0] += p*v0.x; orun[1] += p*v0.y; orun[2] += p*v0.z; orun[3] += p*v0.w;
            orun[4] += p*v1.x; orun[5] += p*v1.y; orun[6] += p*v1.z; orun[7] += p*v1.w;
        }
        mrun = mnew;
    }
    float inv = 1.f / lrun;
    size_t o = ((size_t)(b*MM) + q0 + q) * CC + h*DD + cg*8;
    float4 w0 = {orun[0]*inv, orun[1]*inv, orun[2]*inv, orun[3]*inv};
    float4 w1 = {orun[4]*inv, orun[5]*inv, orun[6]*inv, orun[7]*inv};
    *reinterpret_cast<float4*>(&g_ao[o])     = w0;
    *reinterpret_cast<float4*>(&g_ao[o + 4]) = w1;
}

// ---------------- launch ----------------
extern "C" void kernel_launch(void* const* d_in, const int* in_sizes, int n_in,
                              void* d_out, int out_size)
{
    const float* x       = (const float*)d_in[0];
    const float* mass    = (const float*)d_in[1];
    const float* evals   = (const float*)d_in[2];
    const float* evecs   = (const float*)d_in[3];
    const int*   far_idx = (const int*)  d_in[4];
    const float* t_in    = (const float*)d_in[5];
    const float* t_out   = (const float*)d_in[6];
    const float* gn_w    = (const float*)d_in[7];
    const float* gn_b    = (const float*)d_in[8];
    const float* Wq      = (const float*)d_in[9];
    const float* bq      = (const float*)d_in[10];
    const float* Wk      = (const float*)d_in[11];
    const float* bk      = (const float*)d_in[12];
    const float* Wv      = (const float*)d_in[13];
    const float* bv      = (const float*)d_in[14];
    const float* Wo      = (const float*)d_in[15];
    const float* bo      = (const float*)d_in[16];
    const float* out_w   = (const float*)d_in[17];
    float* out = (float*)d_out;

    static int s_attr_done = 0;
    const int TOB_SMEM  = TOB_SMEM_FLOATS  * 4;   // 51200 B
    const int GEMM_SMEM = GEMM_SMEM_FLOATS * 4;   // 52224 B
    if (!s_attr_done) {
        cudaFuncSetAttribute(k_tobasis_mma, cudaFuncAttributeMaxDynamicSharedMemorySize, TOB_SMEM);
        cudaFuncSetAttribute(k_gemm_mma,    cudaFuncAttributeMaxDynamicSharedMemorySize, GEMM_SMEM);
        s_attr_done = 1;
    }

    float *p_spec1, *p_spec1m, *p_spec2, *p_spec2m, *p_xfar, *p_q, *p_k, *p_v, *p_ao, *p_proj;
    cudaGetSymbolAddress((void**)&p_spec1,  g_spec1);
    cudaGetSymbolAddress((void**)&p_spec1m, g_spec1m);
    cudaGetSymbolAddress((void**)&p_spec2,  g_spec2);
    cudaGetSymbolAddress((void**)&p_spec2m, g_spec2m);
    cudaGetSymbolAddress((void**)&p_xfar,   g_xfar);
    cudaGetSymbolAddress((void**)&p_q,      g_q);
    cudaGetSymbolAddress((void**)&p_k,      g_kmat);
    cudaGetSymbolAddress((void**)&p_v,      g_v);
    cudaGetSymbolAddress((void**)&p_ao,     g_ao);
    cudaGetSymbolAddress((void**)&p_proj,   g_proj);

    const long long AKC = (long long)KK * CC;
    const long long AMC = (long long)MM * CC;
    const long long ANK = (long long)NN * KK;
    const long long ANC = (long long)NN * CC;

    k_zero<<<512, 256>>>();

    // to_basis 1: full N, split-K over 32 chunks of 1024 (3x tf32 mma, pipelined)
    k_tobasis_mma<<<dim3(32, 4, BB), 256, TOB_SMEM>>>(x, mass, evecs, nullptr, p_spec1, 1024, NN);
    k_coef<<<BB*KK, CC>>>(evals, t_in, p_spec1, p_spec1m, nullptr);

    // from_basis 1: only the M gathered rows
    k_gemm_mma<<<dim3(MM/128, 4, BB), 256, GEMM_SMEM>>>(
        evecs, far_idx, ANK,
        p_spec1m, nullptr, nullptr, AKC,
        nullptr, nullptr, nullptr,
        p_xfar, nullptr, nullptr, AMC, KK, 1);

    // GroupNorm
    k_gnstats<<<BB*GG, 256>>>();
    k_gnapply<<<(BB*MM*CC/4)/256, 256>>>(gn_w, gn_b);

    // QKV projections fused (nW=3)
    k_gemm_mma<<<dim3(MM/128, 4, BB*3), 256, GEMM_SMEM>>>(
        p_xfar, nullptr, AMC,
        Wq, Wk, Wv, 0,
        bq, bk, bv,
        p_q, p_k, p_v, AMC, CC, 3);

    // attention
    k_attn<<<dim3(MM/64, HH, BB), 256>>>();

    // output projection
    k_gemm_mma<<<dim3(MM/128, 4, BB), 256, GEMM_SMEM>>>(
        p_ao, nullptr, AMC,
        Wo, nullptr, nullptr, 0,
        bo, nullptr, nullptr,
        p_proj, nullptr, nullptr, AMC, CC, 1);

    // to_basis 2: only the M scattered rows (8 chunks of 128)
    k_tobasis_mma<<<dim3(8, 4, BB), 256, TOB_SMEM>>>(p_proj, mass, evecs, far_idx, p_spec2, 128, MM);
    k_coef<<<BB*KK, CC>>>(evals, t_out, p_spec2, p_spec2m, out_w);

    // from_basis 2: full N output (out_w folded into spec2m)
    k_gemm_mma<<<dim3(NN/128, 4, BB), 256, GEMM_SMEM>>>(
        evecs, nullptr, ANK,
        p_spec2m, nullptr, nullptr, AKC,
        nullptr, nullptr, nullptr,
        out, nullptr, nullptr, ANC, KK, 1);
}

// round 8
// speedup vs baseline: 1.4739x; 1.0764x over previous
#include <cuda_runtime.h>
#include <math.h>
#include <stdint.h>

#define BB 4
#define NN 32768
#define KK 128
#define MM 1024
#define CC 256
#define GG 32
#define HH 8
#define DD 32

// ---------------- scratch (device globals; no allocation allowed) ----------------
__device__ float g_spec1 [BB*KK*CC];
__device__ float g_spec1m[BB*KK*CC];
__device__ float g_spec2 [BB*KK*CC];
__device__ float g_spec2m[BB*KK*CC];
__device__ float g_xfar  [BB*MM*CC];
__device__ float g_q     [BB*MM*CC];
__device__ float g_kmat  [BB*MM*CC];
__device__ float g_v     [BB*MM*CC];
__device__ float g_ao    [BB*MM*CC];
__device__ float g_proj  [BB*MM*CC];
__device__ float g_gnm   [BB*GG];
__device__ float g_gnr   [BB*GG];

// ---------------- tf32 helpers ----------------
__device__ __forceinline__ float tf32r(float x) {
    uint32_t u; asm("cvt.rna.tf32.f32 %0, %1;" : "=r"(u) : "f"(x));
    return __uint_as_float(u);
}

__device__ __forceinline__ void mma8(float d[4], const uint32_t a[4],
                                     uint32_t b0, uint32_t b1) {
    asm volatile(
        "mma.sync.aligned.m16n8k8.row.col.f32.tf32.tf32.f32 "
        "{%0,%1,%2,%3},{%4,%5,%6,%7},{%8,%9},{%0,%1,%2,%3};\n"
        : "+f"(d[0]), "+f"(d[1]), "+f"(d[2]), "+f"(d[3])
        : "r"(a[0]), "r"(a[1]), "r"(a[2]), "r"(a[3]), "r"(b0), "r"(b1));
}

// ---------------- zero the atomic accumulators ----------------
__global__ void k_zero() {
    int i = blockIdx.x * blockDim.x + threadIdx.x;
    if (i < BB*KK*CC) { g_spec1[i] = 0.f; g_spec2[i] = 0.f; }
}

// =====================================================================
// to_basis via 3x-tf32 mma, double-buffered + reg-prefetch pipeline.
// =====================================================================
#define TOB_SMEM_FLOATS (2*16*132*2 + 2*16*68*2)   // 12800 floats = 51200 B

__global__ void __launch_bounds__(256,2) k_tobasis_mma(
    const float* __restrict__ X, const float* __restrict__ mass,
    const float* __restrict__ evecs, const int* __restrict__ gidx,
    float* __restrict__ spec, int chunk, int xRowsPerBatch)
{
    extern __shared__ float sm[];
    float* sEhi = sm;                 // [2][16][132]
    float* sElo = sEhi + 2*16*132;
    float* sXhi = sElo + 2*16*132;    // [2][16][68]
    float* sXlo = sXhi + 2*16*68;
#define EHI(bf,r,c) sEhi[(bf)*2112 + (r)*132 + (c)]
#define ELO(bf,r,c) sElo[(bf)*2112 + (r)*132 + (c)]
#define XHI(bf,r,c) sXhi[(bf)*1088 + (r)*68 + (c)]
#define XLO(bf,r,c) sXlo[(bf)*1088 + (r)*68 + (c)]

    int b  = blockIdx.z;
    int c0 = blockIdx.y * 64;
    int n0 = blockIdx.x * chunk;
    int tid  = threadIdx.x;
    int wid  = tid >> 5, lane = tid & 31;
    int wm   = wid & 3;
    int wn   = wid >> 2;
    int lrow = lane >> 2;
    int lcol = lane & 3;

    int iters = chunk >> 4;

    int er0 = tid >> 5,         ec0 = tid & 31;
    int er1 = (tid + 256) >> 5, ec1 = (tid + 256) & 31;
    int xr  = tid >> 4,         xc  = tid & 15;

    float4 pe0, pe1, px; float pm;
    float4 qe0, qe1, qx; float qm;

#define TOB_FETCH(it, e0, e1, xv, ms) {                                        \
        int nb = (it) << 4;                                                    \
        int n = n0 + nb + er0;                                                 \
        int rr = gidx ? gidx[b*MM + n] : n;                                    \
        e0 = *reinterpret_cast<const float4*>(&evecs[((size_t)b*NN + rr)*KK + ec0*4]); \
        n = n0 + nb + er1;                                                     \
        rr = gidx ? gidx[b*MM + n] : n;                                        \
        e1 = *reinterpret_cast<const float4*>(&evecs[((size_t)b*NN + rr)*KK + ec1*4]); \
        n = n0 + nb + xr;                                                      \
        rr = gidx ? gidx[b*MM + n] : n;                                        \
        ms = mass[(size_t)b*NN + rr];                                          \
        xv = *reinterpret_cast<const float4*>(&X[((size_t)b*xRowsPerBatch + n)*CC + c0 + xc*4]); \
    }

#define TOB_STS(bf, e0, e1, xv, ms) {                                          \
        float4 h, l;                                                           \
        h.x = tf32r(e0.x); l.x = tf32r(e0.x - h.x);                            \
        h.y = tf32r(e0.y); l.y = tf32r(e0.y - h.y);                            \
        h.z = tf32r(e0.z); l.z = tf32r(e0.z - h.z);                            \
        h.w = tf32r(e0.w); l.w = tf32r(e0.w - h.w);                            \
        *reinterpret_cast<float4*>(&EHI(bf, er0, ec0*4)) = h;                  \
        *reinterpret_cast<float4*>(&ELO(bf, er0, ec0*4)) = l;                  \
        h.x = tf32r(e1.x); l.x = tf32r(e1.x - h.x);                            \
        h.y = tf32r(e1.y); l.y = tf32r(e1.y - h.y);                            \
        h.z = tf32r(e1.z); l.z = tf32r(e1.z - h.z);                            \
        h.w = tf32r(e1.w); l.w = tf32r(e1.w - h.w);                            \
        *reinterpret_cast<float4*>(&EHI(bf, er1, ec1*4)) = h;                  \
        *reinterpret_cast<float4*>(&ELO(bf, er1, ec1*4)) = l;                  \
        float4 xs = xv;                                                        \
        xs.x *= ms; xs.y *= ms; xs.z *= ms; xs.w *= ms;                        \
        h.x = tf32r(xs.x); l.x = tf32r(xs.x - h.x);                            \
        h.y = tf32r(xs.y); l.y = tf32r(xs.y - h.y);                            \
        h.z = tf32r(xs.z); l.z = tf32r(xs.z - h.z);                            \
        h.w = tf32r(xs.w); l.w = tf32r(xs.w - h.w);                            \
        *reinterpret_cast<float4*>(&XHI(bf, xr, xc*4)) = h;                    \
        *reinterpret_cast<float4*>(&XLO(bf, xr, xc*4)) = l;                    \
    }

    float acc[2][4][4];
#pragma unroll
    for (int mt = 0; mt < 2; mt++)
#pragma unroll
        for (int nt = 0; nt < 4; nt++)
#pragma unroll
            for (int j = 0; j < 4; j++) acc[mt][nt][j] = 0.f;

    TOB_FETCH(0, pe0, pe1, px, pm);
    TOB_STS(0, pe0, pe1, px, pm);
    if (iters > 1) TOB_FETCH(1, pe0, pe1, px, pm);
    __syncthreads();

    for (int i = 0; i < iters; i++) {
        int cur = i & 1;
        if (i + 2 < iters) TOB_FETCH(i + 2, qe0, qe1, qx, qm);
        if (i + 1 < iters) TOB_STS(cur ^ 1, pe0, pe1, px, pm);

#pragma unroll
        for (int ks = 0; ks < 2; ks++) {
            int kf = ks*8 + lcol;
            uint32_t Aih[2][4], Ail[2][4];
#pragma unroll
            for (int mt = 0; mt < 2; mt++) {
                int m = wm*32 + mt*16 + lrow;
                Aih[mt][0] = __float_as_uint(EHI(cur, kf,   m));
                Aih[mt][1] = __float_as_uint(EHI(cur, kf,   m+8));
                Aih[mt][2] = __float_as_uint(EHI(cur, kf+4, m));
                Aih[mt][3] = __float_as_uint(EHI(cur, kf+4, m+8));
                Ail[mt][0] = __float_as_uint(ELO(cur, kf,   m));
                Ail[mt][1] = __float_as_uint(ELO(cur, kf,   m+8));
                Ail[mt][2] = __float_as_uint(ELO(cur, kf+4, m));
                Ail[mt][3] = __float_as_uint(ELO(cur, kf+4, m+8));
            }
#pragma unroll
            for (int nt = 0; nt < 4; nt++) {
                int c = wn*32 + nt*8 + lrow;
                uint32_t bh0 = __float_as_uint(XHI(cur, kf,   c));
                uint32_t bh1 = __float_as_uint(XHI(cur, kf+4, c));
                uint32_t bl0 = __float_as_uint(XLO(cur, kf,   c));
                uint32_t bl1 = __float_as_uint(XLO(cur, kf+4, c));
#pragma unroll
                for (int mt = 0; mt < 2; mt++) {
                    mma8(acc[mt][nt], Aih[mt], bh0, bh1);
                    mma8(acc[mt][nt], Aih[mt], bl0, bl1);
                    mma8(acc[mt][nt], Ail[mt], bh0, bh1);
                }
            }
        }
        __syncthreads();
        pe0 = qe0; pe1 = qe1; px = qx; pm = qm;
    }

#pragma unroll
    for (int mt = 0; mt < 2; mt++) {
#pragma unroll
        for (int nt = 0; nt < 4; nt++) {
            int row0 = wm*32 + mt*16 + lrow;
            int col  = c0 + wn*32 + nt*8 + 2*lcol;
            float* p0 = &spec[((size_t)b*KK + row0    ) * CC + col];
            float* p1 = &spec[((size_t)b*KK + row0 + 8) * CC + col];
            atomicAdd(p0,     acc[mt][nt][0]);
            atomicAdd(p0 + 1, acc[mt][nt][1]);
            atomicAdd(p1,     acc[mt][nt][2]);
            atomicAdd(p1 + 1, acc[mt][nt][3]);
        }
    }
}

// =====================================================================
// generic 3x-tf32 mma GEMM, double-buffered + reg-prefetch pipeline.
// =====================================================================
#define GEMM_SMEM_FLOATS (2*128*17*2 + 2*16*68*2)   // 13056 floats = 52224 B

__global__ void __launch_bounds__(256,2) k_gemm_mma(
    const float* __restrict__ A, const int* __restrict__ gidx, long long aBatch,
    const float* __restrict__ W0, const float* __restrict__ W1,
    const float* __restrict__ W2, long long wBatch,
    const float* __restrict__ bias0, const float* __restrict__ bias1,
    const float* __restrict__ bias2,
    float* __restrict__ out0, float* __restrict__ out1, float* __restrict__ out2,
    long long oBatch, int Kd, int nW)
{
    extern __shared__ float sm[];
    float* sAhi = sm;                  // [2][128][17]
    float* sAlo = sAhi + 2*128*17;
    float* sBhi = sAlo + 2*128*17;     // [2][16][68]
    float* sBlo = sBhi + 2*16*68;
#define AHI(bf,r,k) sAhi[(bf)*2176 + (r)*17 + (k)]
#define ALO(bf,r,k) sAlo[(bf)*2176 + (r)*17 + (k)]
#define BHI(bf,r,c) sBhi[(bf)*1088 + (r)*68 + (c)]
#define BLO(bf,r,c) sBlo[(bf)*1088 + (r)*68 + (c)]

    int z   = blockIdx.z;
    int b   = z / nW;
    int sel = z - b * nW;
    int r0  = blockIdx.x * 128;
    int c0  = blockIdx.y * 64;

    const float* W    = (sel == 0) ? W0    : (sel == 1) ? W1    : W2;
    const float* bias = (sel == 0) ? bias0 : (sel == 1) ? bias1 : bias2;
    float*       out  = (sel == 0) ? out0  : (sel == 1) ? out1  : out2;

    int tid  = threadIdx.x;
    int wid  = tid >> 5, lane = tid & 31;
    int wm   = wid & 3;
    int wn   = wid >> 2;
    int lrow = lane >> 2;
    int lcol = lane & 3;

    const float* Ab = A + (size_t)b * aBatch;
    const float* Wb = W + (size_t)b * wBatch;
    float*       Ob = out + (size_t)b * oBatch;

    int iters = Kd >> 4;

    int ar0 = tid >> 2,         ak0 = tid & 3;
    int ar1 = (tid + 256) >> 2, ak1 = (tid + 256) & 3;
    int br  = tid >> 4,         bc  = tid & 15;
    int ga0 = gidx ? gidx[b*MM + r0 + ar0] : (r0 + ar0);
    int ga1 = gidx ? gidx[b*MM + r0 + ar1] : (r0 + ar1);

    float4 pa0, pa1, pw;
    float4 qa0, qa1, qw;

#define G_FETCH(it, a0, a1, wv) {                                              \
        int kc = (it) << 4;                                                    \
        a0 = *reinterpret_cast<const float4*>(Ab + (size_t)ga0 * Kd + kc + ak0*4); \
        a1 = *reinterpret_cast<const float4*>(Ab + (size_t)ga1 * Kd + kc + ak1*4); \
        wv = *reinterpret_cast<const float4*>(Wb + (size_t)(kc + br) * CC + c0 + bc*4); \
    }

#define G_STS(bf, a0, a1, wv) {                                                \
        float h;                                                               \
        h = tf32r(a0.x); AHI(bf,ar0,ak0*4+0)=h; ALO(bf,ar0,ak0*4+0)=tf32r(a0.x-h); \
        h = tf32r(a0.y); AHI(bf,ar0,ak0*4+1)=h; ALO(bf,ar0,ak0*4+1)=tf32r(a0.y-h); \
        h = tf32r(a0.z); AHI(bf,ar0,ak0*4+2)=h; ALO(bf,ar0,ak0*4+2)=tf32r(a0.z-h); \
        h = tf32r(a0.w); AHI(bf,ar0,ak0*4+3)=h; ALO(bf,ar0,ak0*4+3)=tf32r(a0.w-h); \
        h = tf32r(a1.x); AHI(bf,ar1,ak1*4+0)=h; ALO(bf,ar1,ak1*4+0)=tf32r(a1.x-h); \
        h = tf32r(a1.y); AHI(bf,ar1,ak1*4+1)=h; ALO(bf,ar1,ak1*4+1)=tf32r(a1.y-h); \
        h = tf32r(a1.z); AHI(bf,ar1,ak1*4+2)=h; ALO(bf,ar1,ak1*4+2)=tf32r(a1.z-h); \
        h = tf32r(a1.w); AHI(bf,ar1,ak1*4+3)=h; ALO(bf,ar1,ak1*4+3)=tf32r(a1.w-h); \
        float4 hh, ll;                                                         \
        hh.x = tf32r(wv.x); ll.x = tf32r(wv.x - hh.x);                         \
        hh.y = tf32r(wv.y); ll.y = tf32r(wv.y - hh.y);                         \
        hh.z = tf32r(wv.z); ll.z = tf32r(wv.z - hh.z);                         \
        hh.w = tf32r(wv.w); ll.w = tf32r(wv.w - hh.w);                         \
        *reinterpret_cast<float4*>(&BHI(bf, br, bc*4)) = hh;                   \
        *reinterpret_cast<float4*>(&BLO(bf, br, bc*4)) = ll;                   \
    }

    float acc[2][4][4];
#pragma unroll
    for (int mt = 0; mt < 2; mt++)
#pragma unroll
        for (int nt = 0; nt < 4; nt++)
#pragma unroll
            for (int j = 0; j < 4; j++) acc[mt][nt][j] = 0.f;

    G_FETCH(0, pa0, pa1, pw);
    G_STS(0, pa0, pa1, pw);
    if (iters > 1) G_FETCH(1, pa0, pa1, pw);
    __syncthreads();

    for (int i = 0; i < iters; i++) {
        int cur = i & 1;
        if (i + 2 < iters) G_FETCH(i + 2, qa0, qa1, qw);
        if (i + 1 < iters) G_STS(cur ^ 1, pa0, pa1, pw);

#pragma unroll
        for (int ks = 0; ks < 2; ks++) {
            int kf = ks*8 + lcol;
            uint32_t Aih[2][4], Ail[2][4];
#pragma unroll
            for (int mt = 0; mt < 2; mt++) {
                int m = wm*32 + mt*16 + lrow;
                Aih[mt][0] = __float_as_uint(AHI(cur, m,   kf));
                Aih[mt][1] = __float_as_uint(AHI(cur, m+8, kf));
                Aih[mt][2] = __float_as_uint(AHI(cur, m,   kf+4));
                Aih[mt][3] = __float_as_uint(AHI(cur, m+8, kf+4));
                Ail[mt][0] = __float_as_uint(ALO(cur, m,   kf));
                Ail[mt][1] = __float_as_uint(ALO(cur, m+8, kf));
                Ail[mt][2] = __float_as_uint(ALO(cur, m,   kf+4));
                Ail[mt][3] = __float_as_uint(ALO(cur, m+8, kf+4));
            }
#pragma unroll
            for (int nt = 0; nt < 4; nt++) {
                int c = wn*32 + nt*8 + lrow;
                uint32_t bh0 = __float_as_uint(BHI(cur, kf,   c));
                uint32_t bh1 = __float_as_uint(BHI(cur, kf+4, c));
                uint32_t bl0 = __float_as_uint(BLO(cur, kf,   c));
                uint32_t bl1 = __float_as_uint(BLO(cur, kf+4, c));
#pragma unroll
                for (int mt = 0; mt < 2; mt++) {
                    mma8(acc[mt][nt], Aih[mt], bh0, bh1);
                    mma8(acc[mt][nt], Aih[mt], bl0, bl1);
                    mma8(acc[mt][nt], Ail[mt], bh0, bh1);
                }
            }
        }
        __syncthreads();
        pa0 = qa0; pa1 = qa1; pw = qw;
    }

#pragma unroll
    for (int mt = 0; mt < 2; mt++) {
#pragma unroll
        for (int nt = 0; nt < 4; nt++) {
            int row0 = r0 + wm*32 + mt*16 + lrow;
            int col  = c0 + wn*32 + nt*8 + 2*lcol;
            float b0v = bias ? bias[col]     : 0.f;
            float b1v = bias ? bias[col + 1] : 0.f;
            float2 v0 = {acc[mt][nt][0] + b0v, acc[mt][nt][1] + b1v};
            float2 v1 = {acc[mt][nt][2] + b0v, acc[mt][nt][3] + b1v};
            *reinterpret_cast<float2*>(&Ob[(size_t)row0       * CC + col]) = v0;
            *reinterpret_cast<float2*>(&Ob[(size_t)(row0 + 8) * CC + col]) = v1;
        }
    }
}

// ---------------- spectral coefficient multiply (+ optional out_w fold) ----------------
__global__ void k_coef(const float* __restrict__ evals, const float* __restrict__ tvec,
                       const float* __restrict__ specin, float* __restrict__ specout,
                       const float* __restrict__ outw)
{
    int bk = blockIdx.x;
    int b = bk >> 7, k = bk & 127;
    int c = threadIdx.x;
    float t = fmaxf(tvec[c], 1e-8f);
    float w = outw ? fmaxf(outw[c], 1e-8f) : 1.f;
    specout[(size_t)bk*CC + c] = expf(-evals[b*KK + k] * t) * specin[(size_t)bk*CC + c] * w;
}

// ---------------- GroupNorm stats ----------------
__global__ void k_gnstats()
{
    int b = blockIdx.x >> 5, g = blockIdx.x & 31;
    int tid = threadIdx.x;
    float s = 0.f, s2 = 0.f;
    for (int e = tid; e < MM*8; e += 256) {
        int m = e >> 3, j = e & 7;
        float v = g_xfar[((size_t)(b*MM + m)) * CC + (g << 3) + j];
        s += v; s2 += v * v;
    }
    __shared__ float rs[256], rq[256];
    rs[tid] = s; rq[tid] = s2;
    __syncthreads();
    for (int o = 128; o > 0; o >>= 1) {
        if (tid < o) { rs[tid] += rs[tid+o]; rq[tid] += rq[tid+o]; }
        __syncthreads();
    }
    if (tid == 0) {
        float mean = rs[0] * (1.f/8192.f);
        float var  = rq[0] * (1.f/8192.f) - mean*mean;
        g_gnm[blockIdx.x] = mean;
        g_gnr[blockIdx.x] = rsqrtf(var + 1e-6f);
    }
}

// ---------------- GroupNorm apply (in place) ----------------
__global__ void k_gnapply(const float* __restrict__ gn_w, const float* __restrict__ gn_b)
{
    int i = blockIdx.x * blockDim.x + threadIdx.x;
    int base = i * 4;
    int c  = base & 255;
    int bm = base >> 8;
    int b  = bm >> 10;
    int g  = c >> 3;
    float mean = g_gnm[b*GG + g];
    float r    = g_gnr[b*GG + g];
    float4 v = *reinterpret_cast<float4*>(&g_xfar[base]);
    v.x = (v.x - mean) * r * gn_w[c+0] + gn_b[c+0];
    v.y = (v.y - mean) * r * gn_w[c+1] + gn_b[c+1];
    v.z = (v.z - mean) * r * gn_w[c+2] + gn_b[c+2];
    v.w = (v.w - mean) * r * gn_w[c+3] + gn_b[c+3];
    *reinterpret_cast<float4*>(&g_xfar[base]) = v;
}

// =====================================================================
// flash attention with 3x-tf32 mma for QK^T and P*V.
// 64-query tiles, 16 key tiles of 64, online softmax.
// =====================================================================
#define ATT_KP 69
#define ATT_VP 36
#define ATT_PP 68
#define ATT_SMEM_FLOATS (2*32*ATT_KP + 2*64*ATT_VP + 2*64*ATT_PP + 256)

__global__ void __launch_bounds__(256,2) k_attn_mma()
{
    extern __shared__ float sm[];
    float* sKhi = sm;                       // [32][69]
    float* sKlo = sKhi + 32*ATT_KP;
    float* sVhi = sKlo + 32*ATT_KP;         // [64][36]
    float* sVlo = sVhi + 64*ATT_VP;
    float* sPhi = sVlo + 64*ATT_VP;         // [64][68] (Q staging too)
    float* sPlo = sPhi + 64*ATT_PP;
    float* sRm  = sPlo + 64*ATT_PP;         // [2][64]
    float* sRl  = sRm + 128;                // [2][64]

    int b = blockIdx.z, h = blockIdx.y, q0 = blockIdx.x * 64;
    int tid = threadIdx.x;
    int wid = tid >> 5, lane = tid & 31;
    int wm = wid & 3, wn = wid >> 2;
    int lrow = lane >> 2, lcol = lane & 3;
    const float scale = 0.17677669529663687f;   // 1/sqrt(32)
    const float L2E = 1.4426950408889634f;

    // ---- stage Q (scaled) hi/lo into P region as [64][36] ----
#pragma unroll
    for (int v = tid; v < 512; v += 256) {
        int r = v >> 3, d0 = (v & 7) * 4;
        float4 qv = *reinterpret_cast<const float4*>(
            &g_q[((size_t)(b*MM) + q0 + r) * CC + h*DD + d0]);
        qv.x *= scale; qv.y *= scale; qv.z *= scale; qv.w *= scale;
        float4 hh, ll;
        hh.x = tf32r(qv.x); ll.x = tf32r(qv.x - hh.x);
        hh.y = tf32r(qv.y); ll.y = tf32r(qv.y - hh.y);
        hh.z = tf32r(qv.z); ll.z = tf32r(qv.z - hh.z);
        hh.w = tf32r(qv.w); ll.w = tf32r(qv.w - hh.w);
        *reinterpret_cast<float4*>(&sPhi[r*ATT_VP + d0]) = hh;
        *reinterpret_cast<float4*>(&sPlo[r*ATT_VP + d0]) = ll;
    }
    __syncthreads();

    // hoist Q fragments to registers
    uint32_t Aqh[4][4], Aql[4][4];
    {
        int m = 16*wm + lrow;
#pragma unroll
        for (int ks = 0; ks < 4; ks++) {
            int kf = ks*8 + lcol;
            Aqh[ks][0] = __float_as_uint(sPhi[m*ATT_VP + kf]);
            Aqh[ks][1] = __float_as_uint(sPhi[(m+8)*ATT_VP + kf]);
            Aqh[ks][2] = __float_as_uint(sPhi[m*ATT_VP + kf + 4]);
            Aqh[ks][3] = __float_as_uint(sPhi[(m+8)*ATT_VP + kf + 4]);
            Aql[ks][0] = __float_as_uint(sPlo[m*ATT_VP + kf]);
            Aql[ks][1] = __float_as_uint(sPlo[(m+8)*ATT_VP + kf]);
            Aql[ks][2] = __float_as_uint(sPlo[m*ATT_VP + kf + 4]);
            Aql[ks][3] = __float_as_uint(sPlo[(m+8)*ATT_VP + kf + 4]);
        }
    }

    float oacc[2][4];
#pragma unroll
    for (int nt = 0; nt < 2; nt++)
#pragma unroll
        for (int j = 0; j < 4; j++) oacc[nt][j] = 0.f;
    float mrun0 = -1e30f, mrun1 = -1e30f, lrun0 = 0.f, lrun1 = 0.f;
    int rbase = 16*wm + lrow;

    for (int kt = 0; kt < 16; kt++) {
        __syncthreads();   // previous tile's smem reads done
        // ---- load K (transposed) and V, split hi/lo ----
#pragma unroll
        for (int v = tid; v < 512; v += 256) {
            int r = v >> 3, d0 = (v & 7) * 4;
            size_t gi = ((size_t)b*MM + kt*64 + r) * CC + h*DD + d0;
            float4 kv = *reinterpret_cast<const float4*>(&g_kmat[gi]);
            float hx;
            hx = tf32r(kv.x); sKhi[(d0+0)*ATT_KP + r] = hx; sKlo[(d0+0)*ATT_KP + r] = tf32r(kv.x - hx);
            hx = tf32r(kv.y); sKhi[(d0+1)*ATT_KP + r] = hx; sKlo[(d0+1)*ATT_KP + r] = tf32r(kv.y - hx);
            hx = tf32r(kv.z); sKhi[(d0+2)*ATT_KP + r] = hx; sKlo[(d0+2)*ATT_KP + r] = tf32r(kv.z - hx);
            hx = tf32r(kv.w); sKhi[(d0+3)*ATT_KP + r] = hx; sKlo[(d0+3)*ATT_KP + r] = tf32r(kv.w - hx);
            float4 vv = *reinterpret_cast<const float4*>(&g_v[gi]);
            float4 hh, ll;
            hh.x = tf32r(vv.x); ll.x = tf32r(vv.x - hh.x);
            hh.y = tf32r(vv.y); ll.y = tf32r(vv.y - hh.y);
            hh.z = tf32r(vv.z); ll.z = tf32r(vv.z - hh.z);
            hh.w = tf32r(vv.w); ll.w = tf32r(vv.w - hh.w);
            *reinterpret_cast<float4*>(&sVhi[r*ATT_VP + d0]) = hh;
            *reinterpret_cast<float4*>(&sVlo[r*ATT_VP + d0]) = ll;
        }
        __syncthreads();

        // ---- QK^T mma ----
        float s[4][4];
#pragma unroll
        for (int nt = 0; nt < 4; nt++)
#pragma unroll
            for (int j = 0; j < 4; j++) s[nt][j] = 0.f;
#pragma unroll
        for (int ks = 0; ks < 4; ks++) {
            int kf = ks*8 + lcol;
#pragma unroll
            for (int nt = 0; nt < 4; nt++) {
                int key = wn*32 + nt*8 + lrow;
                uint32_t bh0 = __float_as_uint(sKhi[kf*ATT_KP + key]);
                uint32_t bh1 = __float_as_uint(sKhi[(kf+4)*ATT_KP + key]);
                uint32_t bl0 = __float_as_uint(sKlo[kf*ATT_KP + key]);
                uint32_t bl1 = __float_as_uint(sKlo[(kf+4)*ATT_KP + key]);
                mma8(s[nt], Aqh[ks], bh0, bh1);
                mma8(s[nt], Aqh[ks], bl0, bl1);
                mma8(s[nt], Aql[ks], bh0, bh1);
            }
        }

        // ---- row max ----
        float t0 = -1e30f, t1 = -1e30f;
#pragma unroll
        for (int nt = 0; nt < 4; nt++) {
            t0 = fmaxf(t0, fmaxf(s[nt][0], s[nt][1]));
            t1 = fmaxf(t1, fmaxf(s[nt][2], s[nt][3]));
        }
        t0 = fmaxf(t0, __shfl_xor_sync(0xffffffff, t0, 1));
        t0 = fmaxf(t0, __shfl_xor_sync(0xffffffff, t0, 2));
        t1 = fmaxf(t1, __shfl_xor_sync(0xffffffff, t1, 1));
        t1 = fmaxf(t1, __shfl_xor_sync(0xffffffff, t1, 2));
        if (lcol == 0) {
            sRm[wn*64 + rbase]     = t0;
            sRm[wn*64 + rbase + 8] = t1;
        }
        __syncthreads();
        float mnew0 = fmaxf(mrun0, fmaxf(sRm[rbase],     sRm[64 + rbase]));
        float mnew1 = fmaxf(mrun1, fmaxf(sRm[rbase + 8], sRm[64 + rbase + 8]));

        // ---- exp, partial sums, write P hi/lo ----
        float ls0 = 0.f, ls1 = 0.f;
#pragma unroll
        for (int nt = 0; nt < 4; nt++) {
            float p0 = exp2f((s[nt][0] - mnew0) * L2E);
            float p1 = exp2f((s[nt][1] - mnew0) * L2E);
            float p2 = exp2f((s[nt][2] - mnew1) * L2E);
            float p3 = exp2f((s[nt][3] - mnew1) * L2E);
            ls0 += p0 + p1;
            ls1 += p2 + p3;
            int col = wn*32 + nt*8 + 2*lcol;
            float h0 = tf32r(p0), h1 = tf32r(p1), h2 = tf32r(p2), h3 = tf32r(p3);
            float2 w0 = {h0, h1}, w1 = {h2, h3};
            float2 z0 = {tf32r(p0 - h0), tf32r(p1 - h1)};
            float2 z1 = {tf32r(p2 - h2), tf32r(p3 - h3)};
            *reinterpret_cast<float2*>(&sPhi[rbase*ATT_PP + col])     = w0;
            *reinterpret_cast<float2*>(&sPhi[(rbase+8)*ATT_PP + col]) = w1;
            *reinterpret_cast<float2*>(&sPlo[rbase*ATT_PP + col])     = z0;
            *reinterpret_cast<float2*>(&sPlo[(rbase+8)*ATT_PP + col]) = z1;
        }
        ls0 += __shfl_xor_sync(0xffffffff, ls0, 1);
        ls0 += __shfl_xor_sync(0xffffffff, ls0, 2);
        ls1 += __shfl_xor_sync(0xffffffff, ls1, 1);
        ls1 += __shfl_xor_sync(0xffffffff, ls1, 2);
        if (lcol == 0) {
            sRl[wn*64 + rbase]     = ls0;
            sRl[wn*64 + rbase + 8] = ls1;
        }
        __syncthreads();
        float lt0 = sRl[rbase]     + sRl[64 + rbase];
        float lt1 = sRl[rbase + 8] + sRl[64 + rbase + 8];
        float c0 = exp2f((mrun0 - mnew0) * L2E);
        float c1 = exp2f((mrun1 - mnew1) * L2E);
        lrun0 = lrun0 * c0 + lt0;
        lrun1 = lrun1 * c1 + lt1;
        mrun0 = mnew0; mrun1 = mnew1;
#pragma unroll
        for (int nt = 0; nt < 2; nt++) {
            oacc[nt][0] *= c0; oacc[nt][1] *= c0;
            oacc[nt][2] *= c1; oacc[nt][3] *= c1;
        }

        // ---- P*V mma ----
#pragma unroll
        for (int ks = 0; ks < 8; ks++) {
            int kf = ks*8 + lcol;
            uint32_t Aph[4], Apl[4];
            Aph[0] = __float_as_uint(sPhi[rbase*ATT_PP + kf]);
            Aph[1] = __float_as_uint(sPhi[(rbase+8)*ATT_PP + kf]);
            Aph[2] = __float_as_uint(sPhi[rbase*ATT_PP + kf + 4]);
            Aph[3] = __float_as_uint(sPhi[(rbase+8)*ATT_PP + kf + 4]);
            Apl[0] = __float_as_uint(sPlo[rbase*ATT_PP + kf]);
            Apl[1] = __float_as_uint(sPlo[(rbase+8)*ATT_PP + kf]);
            Apl[2] = __float_as_uint(sPlo[rbase*ATT_PP + kf + 4]);
            Apl[3] = __float_as_uint(sPlo[(rbase+8)*ATT_PP + kf + 4]);
#pragma unroll
            for (int nt = 0; nt < 2; nt++) {
                int d = wn*16 + nt*8 + lrow;
                uint32_t bh0 = __float_as_uint(sVhi[kf*ATT_VP + d]);
                uint32_t bh1 = __float_as_uint(sVhi[(kf+4)*ATT_VP + d]);
                uint32_t bl0 = __float_as_uint(sVlo[kf*ATT_VP + d]);
                uint32_t bl1 = __float_as_uint(sVlo[(kf+4)*ATT_VP + d]);
                mma8(oacc[nt], Aph, bh0, bh1);
                mma8(oacc[nt], Aph, bl0, bl1);
                mma8(oacc[nt], Apl, bh0, bh1);
            }
        }
    }

    // ---- write output ----
    float i0 = 1.f / lrun0, i1 = 1.f / lrun1;
#pragma unroll
    for (int nt = 0; nt < 2; nt++) {
        int col = h*DD + wn*16 + nt*8 + 2*lcol;
        size_t o0 = ((size_t)(b*MM) + q0 + rbase) * CC + col;
        size_t o1 = ((size_t)(b*MM) + q0 + rbase + 8) * CC + col;
        float2 w0 = {oacc[nt][0]*i0, oacc[nt][1]*i0};
        float2 w1 = {oacc[nt][2]*i1, oacc[nt][3]*i1};
        *reinterpret_cast<float2*>(&g_ao[o0]) = w0;
        *reinterpret_cast<float2*>(&g_ao[o1]) = w1;
    }
}

// ---------------- launch ----------------
extern "C" void kernel_launch(void* const* d_in, const int* in_sizes, int n_in,
                              void* d_out, int out_size)
{
    const float* x       = (const float*)d_in[0];
    const float* mass    = (const float*)d_in[1];
    const float* evals   = (const float*)d_in[2];
    const float* evecs   = (const float*)d_in[3];
    const int*   far_idx = (const int*)  d_in[4];
    const float* t_in    = (const float*)d_in[5];
    const float* t_out   = (const float*)d_in[6];
    const float* gn_w    = (const float*)d_in[7];
    const float* gn_b    = (const float*)d_in[8];
    const float* Wq      = (const float*)d_in[9];
    const float* bq      = (const float*)d_in[10];
    const float* Wk      = (const float*)d_in[11];
    const float* bk      = (const float*)d_in[12];
    const float* Wv      = (const float*)d_in[13];
    const float* bv      = (const float*)d_in[14];
    const float* Wo      = (const float*)d_in[15];
    const float* bo      = (const float*)d_in[16];
    const float* out_w   = (const float*)d_in[17];
    float* out = (float*)d_out;

    static int s_attr_done = 0;
    const int TOB_SMEM  = TOB_SMEM_FLOATS  * 4;
    const int GEMM_SMEM = GEMM_SMEM_FLOATS * 4;
    const int ATT_SMEM  = ATT_SMEM_FLOATS  * 4;
    if (!s_attr_done) {
        cudaFuncSetAttribute(k_tobasis_mma, cudaFuncAttributeMaxDynamicSharedMemorySize, TOB_SMEM);
        cudaFuncSetAttribute(k_gemm_mma,    cudaFuncAttributeMaxDynamicSharedMemorySize, GEMM_SMEM);
        cudaFuncSetAttribute(k_attn_mma,    cudaFuncAttributeMaxDynamicSharedMemorySize, ATT_SMEM);
        s_attr_done = 1;
    }

    float *p_spec1, *p_spec1m, *p_spec2, *p_spec2m, *p_xfar, *p_q, *p_k, *p_v, *p_ao, *p_proj;
    cudaGetSymbolAddress((void**)&p_spec1,  g_spec1);
    cudaGetSymbolAddress((void**)&p_spec1m, g_spec1m);
    cudaGetSymbolAddress((void**)&p_spec2,  g_spec2);
    cudaGetSymbolAddress((void**)&p_spec2m, g_spec2m);
    cudaGetSymbolAddress((void**)&p_xfar,   g_xfar);
    cudaGetSymbolAddress((void**)&p_q,      g_q);
    cudaGetSymbolAddress((void**)&p_k,      g_kmat);
    cudaGetSymbolAddress((void**)&p_v,      g_v);
    cudaGetSymbolAddress((void**)&p_ao,     g_ao);
    cudaGetSymbolAddress((void**)&p_proj,   g_proj);

    const long long AKC = (long long)KK * CC;
    const long long AMC = (long long)MM * CC;
    const long long ANK = (long long)NN * KK;
    const long long ANC = (long long)NN * CC;

    k_zero<<<512, 256>>>();

    // to_basis 1: full N, split-K over 32 chunks of 1024
    k_tobasis_mma<<<dim3(32, 4, BB), 256, TOB_SMEM>>>(x, mass, evecs, nullptr, p_spec1, 1024, NN);
    k_coef<<<BB*KK, CC>>>(evals, t_in, p_spec1, p_spec1m, nullptr);

    // from_basis 1: only the M gathered rows
    k_gemm_mma<<<dim3(MM/128, 4, BB), 256, GEMM_SMEM>>>(
        evecs, far_idx, ANK,
        p_spec1m, nullptr, nullptr, AKC,
        nullptr, nullptr, nullptr,
        p_xfar, nullptr, nullptr, AMC, KK, 1);

    // GroupNorm
    k_gnstats<<<BB*GG, 256>>>();
    k_gnapply<<<(BB*MM*CC/4)/256, 256>>>(gn_w, gn_b);

    // QKV projections fused (nW=3)
    k_gemm_mma<<<dim3(MM/128, 4, BB*3), 256, GEMM_SMEM>>>(
        p_xfar, nullptr, AMC,
        Wq, Wk, Wv, 0,
        bq, bk, bv,
        p_q, p_k, p_v, AMC, CC, 3);

    // attention (tensor-core flash)
    k_attn_mma<<<dim3(MM/64, HH, BB), 256, ATT_SMEM>>>();

    // output projection
    k_gemm_mma<<<dim3(MM/128, 4, BB), 256, GEMM_SMEM>>>(
        p_ao, nullptr, AMC,
        Wo, nullptr, nullptr, 0,
        bo, nullptr, nullptr,
        p_proj, nullptr, nullptr, AMC, CC, 1);

    // to_basis 2: only the M scattered rows
    k_tobasis_mma<<<dim3(8, 4, BB), 256, TOB_SMEM>>>(p_proj, mass, evecs, far_idx, p_spec2, 128, MM);
    k_coef<<<BB*KK, CC>>>(evals, t_out, p_spec2, p_spec2m, out_w);

    // from_basis 2: full N output (out_w folded into spec2m)
    k_gemm_mma<<<dim3(NN/128, 4, BB), 256, GEMM_SMEM>>>(
        evecs, nullptr, ANK,
        p_spec2m, nullptr, nullptr, AKC,
        nullptr, nullptr, nullptr,
        out, nullptr, nullptr, ANC, KK, 1);
}

// round 9
// speedup vs baseline: 1.8970x; 1.2871x over previous
#include <cuda_runtime.h>
#include <math.h>
#include <stdint.h>

#define BB 4
#define NN 32768
#define KK 128
#define MM 1024
#define CC 256
#define GG 32
#define HH 8
#define DD 32

// ---------------- scratch (device globals; no allocation allowed) ----------------
__device__ float g_spec1 [BB*KK*CC];
__device__ float g_spec1m[BB*KK*CC];
__device__ float g_spec2 [BB*KK*CC];
__device__ float g_spec2m[BB*KK*CC];
__device__ float g_xfar  [BB*MM*CC];
__device__ float g_q     [BB*MM*CC];
__device__ float g_kmat  [BB*MM*CC];
__device__ float g_v     [BB*MM*CC];
__device__ float g_ao    [BB*MM*CC];
__device__ float g_proj  [BB*MM*CC];
__device__ float g_gnm   [BB*GG];
__device__ float g_gnr   [BB*GG];

// ---------------- tf32 helpers ----------------
__device__ __forceinline__ float tf32r(float x) {
    uint32_t u; asm("cvt.rna.tf32.f32 %0, %1;" : "=r"(u) : "f"(x));
    return __uint_as_float(u);
}

__device__ __forceinline__ void mma8(float d[4], const uint32_t a[4],
                                     uint32_t b0, uint32_t b1) {
    asm volatile(
        "mma.sync.aligned.m16n8k8.row.col.f32.tf32.tf32.f32 "
        "{%0,%1,%2,%3},{%4,%5,%6,%7},{%8,%9},{%0,%1,%2,%3};\n"
        : "+f"(d[0]), "+f"(d[1]), "+f"(d[2]), "+f"(d[3])
        : "r"(a[0]), "r"(a[1]), "r"(a[2]), "r"(a[3]), "r"(b0), "r"(b1));
}

// ---------------- zero the atomic accumulators ----------------
__global__ void k_zero() {
    int i = blockIdx.x * blockDim.x + threadIdx.x;
    if (i < BB*KK*CC) { g_spec1[i] = 0.f; g_spec2[i] = 0.f; }
}

// =====================================================================
// to_basis via 3x-tf32 mma, raw-fp32 smem + register hi/lo split.
// spec[b,k,c] += sum_n E[b,row(n),k]*mass*X[b,n,c]
// smem: E raw [2][16][136] (layout [n][k]), X raw [2][16][72]
// =====================================================================
#define TOB_SMEM_FLOATS (2*16*136 + 2*16*72)   // 6656 floats = 26624 B

__global__ void __launch_bounds__(256,2) k_tobasis_mma(
    const float* __restrict__ X, const float* __restrict__ mass,
    const float* __restrict__ evecs, const int* __restrict__ gidx,
    float* __restrict__ spec, int chunk, int xRowsPerBatch)
{
    extern __shared__ float sm[];
    float* sE = sm;                 // [2][16][136]
    float* sX = sE + 2*16*136;      // [2][16][72]
#define SE(bf,r,c) sE[(bf)*2176 + (r)*136 + (c)]
#define SX(bf,r,c) sX[(bf)*1152 + (r)*72 + (c)]

    int b  = blockIdx.z;
    int c0 = blockIdx.y * 64;
    int n0 = blockIdx.x * chunk;
    int tid  = threadIdx.x;
    int wid  = tid >> 5, lane = tid & 31;
    int wm   = wid & 3;
    int wn   = wid >> 2;
    int lrow = lane >> 2;
    int lcol = lane & 3;

    int iters = chunk >> 4;

    int er0 = tid >> 5,         ec0 = tid & 31;
    int er1 = (tid + 256) >> 5, ec1 = (tid + 256) & 31;
    int xr  = tid >> 4,         xc  = tid & 15;

    float4 pe0, pe1, px; float pm;
    float4 qe0, qe1, qx; float qm;

#define TOB_FETCH(it, e0, e1, xv, ms) {                                        \
        int n = n0 + ((it) << 4) + er0;                                        \
        int rr = gidx ? gidx[b*MM + n] : n;                                    \
        e0 = *reinterpret_cast<const float4*>(&evecs[((size_t)b*NN + rr)*KK + ec0*4]); \
        n = n0 + ((it) << 4) + er1;                                            \
        rr = gidx ? gidx[b*MM + n] : n;                                        \
        e1 = *reinterpret_cast<const float4*>(&evecs[((size_t)b*NN + rr)*KK + ec1*4]); \
        n = n0 + ((it) << 4) + xr;                                             \
        rr = gidx ? gidx[b*MM + n] : n;                                        \
        ms = mass[(size_t)b*NN + rr];                                          \
        xv = *reinterpret_cast<const float4*>(&X[((size_t)b*xRowsPerBatch + n)*CC + c0 + xc*4]); \
    }

#define TOB_STS(bf, e0, e1, xv, ms) {                                          \
        *reinterpret_cast<float4*>(&SE(bf, er0, ec0*4)) = e0;                  \
        *reinterpret_cast<float4*>(&SE(bf, er1, ec1*4)) = e1;                  \
        float4 xs = xv;                                                        \
        xs.x *= ms; xs.y *= ms; xs.z *= ms; xs.w *= ms;                        \
        *reinterpret_cast<float4*>(&SX(bf, xr, xc*4)) = xs;                    \
    }

    float acc[2][4][4];
#pragma unroll
    for (int mt = 0; mt < 2; mt++)
#pragma unroll
        for (int nt = 0; nt < 4; nt++)
#pragma unroll
            for (int j = 0; j < 4; j++) acc[mt][nt][j] = 0.f;

    TOB_FETCH(0, pe0, pe1, px, pm);
    TOB_STS(0, pe0, pe1, px, pm);
    if (iters > 1) TOB_FETCH(1, pe0, pe1, px, pm);
    __syncthreads();

    for (int i = 0; i < iters; i++) {
        int cur = i & 1;
        if (i + 2 < iters) TOB_FETCH(i + 2, qe0, qe1, qx, qm);
        if (i + 1 < iters) TOB_STS(cur ^ 1, pe0, pe1, px, pm);

#pragma unroll
        for (int ks = 0; ks < 2; ks++) {
            int kf = ks*8 + lcol;
            uint32_t Aih[2][4], Ail[2][4];
#pragma unroll
            for (int mt = 0; mt < 2; mt++) {
                int m = wm*32 + mt*16 + lrow;
                // raw A fragments: E[kf][m] layout
                float r0 = SE(cur, kf,   m);
                float r1 = SE(cur, kf,   m+8);
                float r2 = SE(cur, kf+4, m);
                float r3 = SE(cur, kf+4, m+8);
                float h0 = tf32r(r0), h1 = tf32r(r1), h2 = tf32r(r2), h3 = tf32r(r3);
                Aih[mt][0] = __float_as_uint(h0);
                Aih[mt][1] = __float_as_uint(h1);
                Aih[mt][2] = __float_as_uint(h2);
                Aih[mt][3] = __float_as_uint(h3);
                Ail[mt][0] = __float_as_uint(r0 - h0);
                Ail[mt][1] = __float_as_uint(r1 - h1);
                Ail[mt][2] = __float_as_uint(r2 - h2);
                Ail[mt][3] = __float_as_uint(r3 - h3);
            }
#pragma unroll
            for (int nt = 0; nt < 4; nt++) {
                int c = wn*32 + nt*8 + lrow;
                float b0r = SX(cur, kf,   c);
                float b1r = SX(cur, kf+4, c);
                float hb0 = tf32r(b0r), hb1 = tf32r(b1r);
                uint32_t bh0 = __float_as_uint(hb0);
                uint32_t bh1 = __float_as_uint(hb1);
                uint32_t bl0 = __float_as_uint(b0r - hb0);
                uint32_t bl1 = __float_as_uint(b1r - hb1);
#pragma unroll
                for (int mt = 0; mt < 2; mt++) {
                    mma8(acc[mt][nt], Aih[mt], bh0, bh1);
                    mma8(acc[mt][nt], Aih[mt], bl0, bl1);
                    mma8(acc[mt][nt], Ail[mt], bh0, bh1);
                }
            }
        }
        __syncthreads();
        pe0 = qe0; pe1 = qe1; px = qx; pm = qm;
    }

#pragma unroll
    for (int mt = 0; mt < 2; mt++) {
#pragma unroll
        for (int nt = 0; nt < 4; nt++) {
            int row0 = wm*32 + mt*16 + lrow;
            int col  = c0 + wn*32 + nt*8 + 2*lcol;
            float* p0 = &spec[((size_t)b*KK + row0    ) * CC + col];
            float* p1 = &spec[((size_t)b*KK + row0 + 8) * CC + col];
            atomicAdd(p0,     acc[mt][nt][0]);
            atomicAdd(p0 + 1, acc[mt][nt][1]);
            atomicAdd(p1,     acc[mt][nt][2]);
            atomicAdd(p1 + 1, acc[mt][nt][3]);
        }
    }
}

// =====================================================================
// generic 3x-tf32 mma GEMM, raw-fp32 smem + register hi/lo split.
// smem: A raw [2][128][20], B raw [2][16][72]
// =====================================================================
#define GEMM_SMEM_FLOATS (2*128*20 + 2*16*72)   // 7424 floats = 29696 B

__global__ void __launch_bounds__(256,2) k_gemm_mma(
    const float* __restrict__ A, const int* __restrict__ gidx, long long aBatch,
    const float* __restrict__ W0, const float* __restrict__ W1,
    const float* __restrict__ W2, long long wBatch,
    const float* __restrict__ bias0, const float* __restrict__ bias1,
    const float* __restrict__ bias2,
    float* __restrict__ out0, float* __restrict__ out1, float* __restrict__ out2,
    long long oBatch, int Kd, int nW)
{
    extern __shared__ float sm[];
    float* sA = sm;                 // [2][128][20]
    float* sB = sA + 2*128*20;      // [2][16][72]
#define SA(bf,r,k) sA[(bf)*2560 + (r)*20 + (k)]
#define SB(bf,r,c) sB[(bf)*1152 + (r)*72 + (c)]

    int z   = blockIdx.z;
    int b   = z / nW;
    int sel = z - b * nW;
    int r0  = blockIdx.x * 128;
    int c0  = blockIdx.y * 64;

    const float* W    = (sel == 0) ? W0    : (sel == 1) ? W1    : W2;
    const float* bias = (sel == 0) ? bias0 : (sel == 1) ? bias1 : bias2;
    float*       out  = (sel == 0) ? out0  : (sel == 1) ? out1  : out2;

    int tid  = threadIdx.x;
    int wid  = tid >> 5, lane = tid & 31;
    int wm   = wid & 3;
    int wn   = wid >> 2;
    int lrow = lane >> 2;
    int lcol = lane & 3;

    const float* Ab = A + (size_t)b * aBatch;
    const float* Wb = W + (size_t)b * wBatch;
    float*       Ob = out + (size_t)b * oBatch;

    int iters = Kd >> 4;

    int ar0 = tid >> 2,         ak0 = tid & 3;
    int ar1 = (tid + 256) >> 2, ak1 = (tid + 256) & 3;
    int br  = tid >> 4,         bc  = tid & 15;
    int ga0 = gidx ? gidx[b*MM + r0 + ar0] : (r0 + ar0);
    int ga1 = gidx ? gidx[b*MM + r0 + ar1] : (r0 + ar1);

    float4 pa0, pa1, pw;
    float4 qa0, qa1, qw;

#define G_FETCH(it, a0, a1, wv) {                                              \
        int kc = (it) << 4;                                                    \
        a0 = *reinterpret_cast<const float4*>(Ab + (size_t)ga0 * Kd + kc + ak0*4); \
        a1 = *reinterpret_cast<const float4*>(Ab + (size_t)ga1 * Kd + kc + ak1*4); \
        wv = *reinterpret_cast<const float4*>(Wb + (size_t)(kc + br) * CC + c0 + bc*4); \
    }

#define G_STS(bf, a0, a1, wv) {                                                \
        *reinterpret_cast<float4*>(&SA(bf, ar0, ak0*4)) = a0;                  \
        *reinterpret_cast<float4*>(&SA(bf, ar1, ak1*4)) = a1;                  \
        *reinterpret_cast<float4*>(&SB(bf, br, bc*4)) = wv;                    \
    }

    float acc[2][4][4];
#pragma unroll
    for (int mt = 0; mt < 2; mt++)
#pragma unroll
        for (int nt = 0; nt < 4; nt++)
#pragma unroll
            for (int j = 0; j < 4; j++) acc[mt][nt][j] = 0.f;

    G_FETCH(0, pa0, pa1, pw);
    G_STS(0, pa0, pa1, pw);
    if (iters > 1) G_FETCH(1, pa0, pa1, pw);
    __syncthreads();

    for (int i = 0; i < iters; i++) {
        int cur = i & 1;
        if (i + 2 < iters) G_FETCH(i + 2, qa0, qa1, qw);
        if (i + 1 < iters) G_STS(cur ^ 1, pa0, pa1, pw);

#pragma unroll
        for (int ks = 0; ks < 2; ks++) {
            int kf = ks*8 + lcol;
            uint32_t Aih[2][4], Ail[2][4];
#pragma unroll
            for (int mt = 0; mt < 2; mt++) {
                int m = wm*32 + mt*16 + lrow;
                float r0 = SA(cur, m,   kf);
                float r1 = SA(cur, m+8, kf);
                float r2 = SA(cur, m,   kf+4);
                float r3 = SA(cur, m+8, kf+4);
                float h0 = tf32r(r0), h1 = tf32r(r1), h2 = tf32r(r2), h3 = tf32r(r3);
                Aih[mt][0] = __float_as_uint(h0);
                Aih[mt][1] = __float_as_uint(h1);
                Aih[mt][2] = __float_as_uint(h2);
                Aih[mt][3] = __float_as_uint(h3);
                Ail[mt][0] = __float_as_uint(r0 - h0);
                Ail[mt][1] = __float_as_uint(r1 - h1);
                Ail[mt][2] = __float_as_uint(r2 - h2);
                Ail[mt][3] = __float_as_uint(r3 - h3);
            }
#pragma unroll
            for (int nt = 0; nt < 4; nt++) {
                int c = wn*32 + nt*8 + lrow;
                float b0r = SB(cur, kf,   c);
                float b1r = SB(cur, kf+4, c);
                float hb0 = tf32r(b0r), hb1 = tf32r(b1r);
                uint32_t bh0 = __float_as_uint(hb0);
                uint32_t bh1 = __float_as_uint(hb1);
                uint32_t bl0 = __float_as_uint(b0r - hb0);
                uint32_t bl1 = __float_as_uint(b1r - hb1);
#pragma unroll
                for (int mt = 0; mt < 2; mt++) {
                    mma8(acc[mt][nt], Aih[mt], bh0, bh1);
                    mma8(acc[mt][nt], Aih[mt], bl0, bl1);
                    mma8(acc[mt][nt], Ail[mt], bh0, bh1);
                }
            }
        }
        __syncthreads();
        pa0 = qa0; pa1 = qa1; pw = qw;
    }

#pragma unroll
    for (int mt = 0; mt < 2; mt++) {
#pragma unroll
        for (int nt = 0; nt < 4; nt++) {
            int row0 = r0 + wm*32 + mt*16 + lrow;
            int col  = c0 + wn*32 + nt*8 + 2*lcol;
            float b0v = bias ? bias[col]     : 0.f;
            float b1v = bias ? bias[col + 1] : 0.f;
            float2 v0 = {acc[mt][nt][0] + b0v, acc[mt][nt][1] + b1v};
            float2 v1 = {acc[mt][nt][2] + b0v, acc[mt][nt][3] + b1v};
            *reinterpret_cast<float2*>(&Ob[(size_t)row0       * CC + col]) = v0;
            *reinterpret_cast<float2*>(&Ob[(size_t)(row0 + 8) * CC + col]) = v1;
        }
    }
}

// ---------------- spectral coefficient multiply (+ optional out_w fold) ----------------
__global__ void k_coef(const float* __restrict__ evals, const float* __restrict__ tvec,
                       const float* __restrict__ specin, float* __restrict__ specout,
                       const float* __restrict__ outw)
{
    int bk = blockIdx.x;
    int b = bk >> 7, k = bk & 127;
    int c = threadIdx.x;
    float t = fmaxf(tvec[c], 1e-8f);
    float w = outw ? fmaxf(outw[c], 1e-8f) : 1.f;
    specout[(size_t)bk*CC + c] = expf(-evals[b*KK + k] * t) * specin[(size_t)bk*CC + c] * w;
}

// ---------------- GroupNorm stats ----------------
__global__ void k_gnstats()
{
    int b = blockIdx.x >> 5, g = blockIdx.x & 31;
    int tid = threadIdx.x;
    float s = 0.f, s2 = 0.f;
    for (int e = tid; e < MM*8; e += 256) {
        int m = e >> 3, j = e & 7;
        float v = g_xfar[((size_t)(b*MM + m)) * CC + (g << 3) + j];
        s += v; s2 += v * v;
    }
    __shared__ float rs[256], rq[256];
    rs[tid] = s; rq[tid] = s2;
    __syncthreads();
    for (int o = 128; o > 0; o >>= 1) {
        if (tid < o) { rs[tid] += rs[tid+o]; rq[tid] += rq[tid+o]; }
        __syncthreads();
    }
    if (tid == 0) {
        float mean = rs[0] * (1.f/8192.f);
        float var  = rq[0] * (1.f/8192.f) - mean*mean;
        g_gnm[blockIdx.x] = mean;
        g_gnr[blockIdx.x] = rsqrtf(var + 1e-6f);
    }
}

// ---------------- GroupNorm apply (in place) ----------------
__global__ void k_gnapply(const float* __restrict__ gn_w, const float* __restrict__ gn_b)
{
    int i = blockIdx.x * blockDim.x + threadIdx.x;
    int base = i * 4;
    int c  = base & 255;
    int bm = base >> 8;
    int b  = bm >> 10;
    int g  = c >> 3;
    float mean = g_gnm[b*GG + g];
    float r    = g_gnr[b*GG + g];
    float4 v = *reinterpret_cast<float4*>(&g_xfar[base]);
    v.x = (v.x - mean) * r * gn_w[c+0] + gn_b[c+0];
    v.y = (v.y - mean) * r * gn_w[c+1] + gn_b[c+1];
    v.z = (v.z - mean) * r * gn_w[c+2] + gn_b[c+2];
    v.w = (v.w - mean) * r * gn_w[c+3] + gn_b[c+3];
    *reinterpret_cast<float4*>(&g_xfar[base]) = v;
}

// =====================================================================
// flash attention with 3x-tf32 mma (unchanged from round 8 — protected win)
// =====================================================================
#define ATT_KP 69
#define ATT_VP 36
#define ATT_PP 68
#define ATT_SMEM_FLOATS (2*32*ATT_KP + 2*64*ATT_VP + 2*64*ATT_PP + 256)

__global__ void __launch_bounds__(256,2) k_attn_mma()
{
    extern __shared__ float sm[];
    float* sKhi = sm;                       // [32][69]
    float* sKlo = sKhi + 32*ATT_KP;
    float* sVhi = sKlo + 32*ATT_KP;         // [64][36]
    float* sVlo = sVhi + 64*ATT_VP;
    float* sPhi = sVlo + 64*ATT_VP;         // [64][68] (Q staging too)
    float* sPlo = sPhi + 64*ATT_PP;
    float* sRm  = sPlo + 64*ATT_PP;         // [2][64]
    float* sRl  = sRm + 128;                // [2][64]

    int b = blockIdx.z, h = blockIdx.y, q0 = blockIdx.x * 64;
    int tid = threadIdx.x;
    int wid = tid >> 5, lane = tid & 31;
    int wm = wid & 3, wn = wid >> 2;
    int lrow = lane >> 2, lcol = lane & 3;
    const float scale = 0.17677669529663687f;   // 1/sqrt(32)
    const float L2E = 1.4426950408889634f;

#pragma unroll
    for (int v = tid; v < 512; v += 256) {
        int r = v >> 3, d0 = (v & 7) * 4;
        float4 qv = *reinterpret_cast<const float4*>(
            &g_q[((size_t)(b*MM) + q0 + r) * CC + h*DD + d0]);
        qv.x *= scale; qv.y *= scale; qv.z *= scale; qv.w *= scale;
        float4 hh, ll;
        hh.x = tf32r(qv.x); ll.x = tf32r(qv.x - hh.x);
        hh.y = tf32r(qv.y); ll.y = tf32r(qv.y - hh.y);
        hh.z = tf32r(qv.z); ll.z = tf32r(qv.z - hh.z);
        hh.w = tf32r(qv.w); ll.w = tf32r(qv.w - hh.w);
        *reinterpret_cast<float4*>(&sPhi[r*ATT_VP + d0]) = hh;
        *reinterpret_cast<float4*>(&sPlo[r*ATT_VP + d0]) = ll;
    }
    __syncthreads();

    uint32_t Aqh[4][4], Aql[4][4];
    {
        int m = 16*wm + lrow;
#pragma unroll
        for (int ks = 0; ks < 4; ks++) {
            int kf = ks*8 + lcol;
            Aqh[ks][0] = __float_as_uint(sPhi[m*ATT_VP + kf]);
            Aqh[ks][1] = __float_as_uint(sPhi[(m+8)*ATT_VP + kf]);
            Aqh[ks][2] = __float_as_uint(sPhi[m*ATT_VP + kf + 4]);
            Aqh[ks][3] = __float_as_uint(sPhi[(m+8)*ATT_VP + kf + 4]);
            Aql[ks][0] = __float_as_uint(sPlo[m*ATT_VP + kf]);
            Aql[ks][1] = __float_as_uint(sPlo[(m+8)*ATT_VP + kf]);
            Aql[ks][2] = __float_as_uint(sPlo[m*ATT_VP + kf + 4]);
            Aql[ks][3] = __float_as_uint(sPlo[(m+8)*ATT_VP + kf + 4]);
        }
    }

    float oacc[2][4];
#pragma unroll
    for (int nt = 0; nt < 2; nt++)
#pragma unroll
        for (int j = 0; j < 4; j++) oacc[nt][j] = 0.f;
    float mrun0 = -1e30f, mrun1 = -1e30f, lrun0 = 0.f, lrun1 = 0.f;
    int rbase = 16*wm + lrow;

    for (int kt = 0; kt < 16; kt++) {
        __syncthreads();
#pragma unroll
        for (int v = tid; v < 512; v += 256) {
            int r = v >> 3, d0 = (v & 7) * 4;
            size_t gi = ((size_t)b*MM + kt*64 + r) * CC + h*DD + d0;
            float4 kv = *reinterpret_cast<const float4*>(&g_kmat[gi]);
            float hx;
            hx = tf32r(kv.x); sKhi[(d0+0)*ATT_KP + r] = hx; sKlo[(d0+0)*ATT_KP + r] = tf32r(kv.x - hx);
            hx = tf32r(kv.y); sKhi[(d0+1)*ATT_KP + r] = hx; sKlo[(d0+1)*ATT_KP + r] = tf32r(kv.y - hx);
            hx = tf32r(kv.z); sKhi[(d0+2)*ATT_KP + r] = hx; sKlo[(d0+2)*ATT_KP + r] = tf32r(kv.z - hx);
            hx = tf32r(kv.w); sKhi[(d0+3)*ATT_KP + r] = hx; sKlo[(d0+3)*ATT_KP + r] = tf32r(kv.w - hx);
            float4 vv = *reinterpret_cast<const float4*>(&g_v[gi]);
            float4 hh, ll;
            hh.x = tf32r(vv.x); ll.x = tf32r(vv.x - hh.x);
            hh.y = tf32r(vv.y); ll.y = tf32r(vv.y - hh.y);
            hh.z = tf32r(vv.z); ll.z = tf32r(vv.z - hh.z);
            hh.w = tf32r(vv.w); ll.w = tf32r(vv.w - hh.w);
            *reinterpret_cast<float4*>(&sVhi[r*ATT_VP + d0]) = hh;
            *reinterpret_cast<float4*>(&sVlo[r*ATT_VP + d0]) = ll;
        }
        __syncthreads();

        float s[4][4];
#pragma unroll
        for (int nt = 0; nt < 4; nt++)
#pragma unroll
            for (int j = 0; j < 4; j++) s[nt][j] = 0.f;
#pragma unroll
        for (int ks = 0; ks < 4; ks++) {
            int kf = ks*8 + lcol;
#pragma unroll
            for (int nt = 0; nt < 4; nt++) {
                int key = wn*32 + nt*8 + lrow;
                uint32_t bh0 = __float_as_uint(sKhi[kf*ATT_KP + key]);
                uint32_t bh1 = __float_as_uint(sKhi[(kf+4)*ATT_KP + key]);
                uint32_t bl0 = __float_as_uint(sKlo[kf*ATT_KP + key]);
                uint32_t bl1 = __float_as_uint(sKlo[(kf+4)*ATT_KP + key]);
                mma8(s[nt], Aqh[ks], bh0, bh1);
                mma8(s[nt], Aqh[ks], bl0, bl1);
                mma8(s[nt], Aql[ks], bh0, bh1);
            }
        }

        float t0 = -1e30f, t1 = -1e30f;
#pragma unroll
        for (int nt = 0; nt < 4; nt++) {
            t0 = fmaxf(t0, fmaxf(s[nt][0], s[nt][1]));
            t1 = fmaxf(t1, fmaxf(s[nt][2], s[nt][3]));
        }
        t0 = fmaxf(t0, __shfl_xor_sync(0xffffffff, t0, 1));
        t0 = fmaxf(t0, __shfl_xor_sync(0xffffffff, t0, 2));
        t1 = fmaxf(t1, __shfl_xor_sync(0xffffffff, t1, 1));
        t1 = fmaxf(t1, __shfl_xor_sync(0xffffffff, t1, 2));
        if (lcol == 0) {
            sRm[wn*64 + rbase]     = t0;
            sRm[wn*64 + rbase + 8] = t1;
        }
        __syncthreads();
        float mnew0 = fmaxf(mrun0, fmaxf(sRm[rbase],     sRm[64 + rbase]));
        float mnew1 = fmaxf(mrun1, fmaxf(sRm[rbase + 8], sRm[64 + rbase + 8]));

        float ls0 = 0.f, ls1 = 0.f;
#pragma unroll
        for (int nt = 0; nt < 4; nt++) {
            float p0 = exp2f((s[nt][0] - mnew0) * L2E);
            float p1 = exp2f((s[nt][1] - mnew0) * L2E);
            float p2 = exp2f((s[nt][2] - mnew1) * L2E);
            float p3 = exp2f((s[nt][3] - mnew1) * L2E);
            ls0 += p0 + p1;
            ls1 += p2 + p3;
            int col = wn*32 + nt*8 + 2*lcol;
            float h0 = tf32r(p0), h1 = tf32r(p1), h2 = tf32r(p2), h3 = tf32r(p3);
            float2 w0 = {h0, h1}, w1 = {h2, h3};
            float2 z0 = {tf32r(p0 - h0), tf32r(p1 - h1)};
            float2 z1 = {tf32r(p2 - h2), tf32r(p3 - h3)};
            *reinterpret_cast<float2*>(&sPhi[rbase*ATT_PP + col])     = w0;
            *reinterpret_cast<float2*>(&sPhi[(rbase+8)*ATT_PP + col]) = w1;
            *reinterpret_cast<float2*>(&sPlo[rbase*ATT_PP + col])     = z0;
            *reinterpret_cast<float2*>(&sPlo[(rbase+8)*ATT_PP + col]) = z1;
        }
        ls0 += __shfl_xor_sync(0xffffffff, ls0, 1);
        ls0 += __shfl_xor_sync(0xffffffff, ls0, 2);
        ls1 += __shfl_xor_sync(0xffffffff, ls1, 1);
        ls1 += __shfl_xor_sync(0xffffffff, ls1, 2);
        if (lcol == 0) {
            sRl[wn*64 + rbase]     = ls0;
            sRl[wn*64 + rbase + 8] = ls1;
        }
        __syncthreads();
        float lt0 = sRl[rbase]     + sRl[64 + rbase];
        float lt1 = sRl[rbase + 8] + sRl[64 + rbase + 8];
        float c0 = exp2f((mrun0 - mnew0) * L2E);
        float c1 = exp2f((mrun1 - mnew1) * L2E);
        lrun0 = lrun0 * c0 + lt0;
        lrun1 = lrun1 * c1 + lt1;
        mrun0 = mnew0; mrun1 = mnew1;
#pragma unroll
        for (int nt = 0; nt < 2; nt++) {
            oacc[nt][0] *= c0; oacc[nt][1] *= c0;
            oacc[nt][2] *= c1; oacc[nt][3] *= c1;
        }

#pragma unroll
        for (int ks = 0; ks < 8; ks++) {
            int kf = ks*8 + lcol;
            uint32_t Aph[4], Apl[4];
            Aph[0] = __float_as_uint(sPhi[rbase*ATT_PP + kf]);
            Aph[1] = __float_as_uint(sPhi[(rbase+8)*ATT_PP + kf]);
            Aph[2] = __float_as_uint(sPhi[rbase*ATT_PP + kf + 4]);
            Aph[3] = __float_as_uint(sPhi[(rbase+8)*ATT_PP + kf + 4]);
            Apl[0] = __float_as_uint(sPlo[rbase*ATT_PP + kf]);
            Apl[1] = __float_as_uint(sPlo[(rbase+8)*ATT_PP + kf]);
            Apl[2] = __float_as_uint(sPlo[rbase*ATT_PP + kf + 4]);
            Apl[3] = __float_as_uint(sPlo[(rbase+8)*ATT_PP + kf + 4]);
#pragma unroll
            for (int nt = 0; nt < 2; nt++) {
                int d = wn*16 + nt*8 + lrow;
                uint32_t bh0 = __float_as_uint(sVhi[kf*ATT_VP + d]);
                uint32_t bh1 = __float_as_uint(sVhi[(kf+4)*ATT_VP + d]);
                uint32_t bl0 = __float_as_uint(sVlo[kf*ATT_VP + d]);
                uint32_t bl1 = __float_as_uint(sVlo[(kf+4)*ATT_VP + d]);
                mma8(oacc[nt], Aph, bh0, bh1);
                mma8(oacc[nt], Aph, bl0, bl1);
                mma8(oacc[nt], Apl, bh0, bh1);
            }
        }
    }

    float i0 = 1.f / lrun0, i1 = 1.f / lrun1;
#pragma unroll
    for (int nt = 0; nt < 2; nt++) {
        int col = h*DD + wn*16 + nt*8 + 2*lcol;
        size_t o0 = ((size_t)(b*MM) + q0 + rbase) * CC + col;
        size_t o1 = ((size_t)(b*MM) + q0 + rbase + 8) * CC + col;
        float2 w0 = {oacc[nt][0]*i0, oacc[nt][1]*i0};
        float2 w1 = {oacc[nt][2]*i1, oacc[nt][3]*i1};
        *reinterpret_cast<float2*>(&g_ao[o0]) = w0;
        *reinterpret_cast<float2*>(&g_ao[o1]) = w1;
    }
}

// ---------------- launch ----------------
extern "C" void kernel_launch(void* const* d_in, const int* in_sizes, int n_in,
                              void* d_out, int out_size)
{
    const float* x       = (const float*)d_in[0];
    const float* mass    = (const float*)d_in[1];
    const float* evals   = (const float*)d_in[2];
    const float* evecs   = (const float*)d_in[3];
    const int*   far_idx = (const int*)  d_in[4];
    const float* t_in    = (const float*)d_in[5];
    const float* t_out   = (const float*)d_in[6];
    const float* gn_w    = (const float*)d_in[7];
    const float* gn_b    = (const float*)d_in[8];
    const float* Wq      = (const float*)d_in[9];
    const float* bq      = (const float*)d_in[10];
    const float* Wk      = (const float*)d_in[11];
    const float* bk      = (const float*)d_in[12];
    const float* Wv      = (const float*)d_in[13];
    const float* bv      = (const float*)d_in[14];
    const float* Wo      = (const float*)d_in[15];
    const float* bo      = (const float*)d_in[16];
    const float* out_w   = (const float*)d_in[17];
    float* out = (float*)d_out;

    static int s_attr_done = 0;
    const int TOB_SMEM  = TOB_SMEM_FLOATS  * 4;
    const int GEMM_SMEM = GEMM_SMEM_FLOATS * 4;
    const int ATT_SMEM  = ATT_SMEM_FLOATS  * 4;
    if (!s_attr_done) {
        cudaFuncSetAttribute(k_tobasis_mma, cudaFuncAttributeMaxDynamicSharedMemorySize, TOB_SMEM);
        cudaFuncSetAttribute(k_gemm_mma,    cudaFuncAttributeMaxDynamicSharedMemorySize, GEMM_SMEM);
        cudaFuncSetAttribute(k_attn_mma,    cudaFuncAttributeMaxDynamicSharedMemorySize, ATT_SMEM);
        s_attr_done = 1;
    }

    float *p_spec1, *p_spec1m, *p_spec2, *p_spec2m, *p_xfar, *p_q, *p_k, *p_v, *p_ao, *p_proj;
    cudaGetSymbolAddress((void**)&p_spec1,  g_spec1);
    cudaGetSymbolAddress((void**)&p_spec1m, g_spec1m);
    cudaGetSymbolAddress((void**)&p_spec2,  g_spec2);
    cudaGetSymbolAddress((void**)&p_spec2m, g_spec2m);
    cudaGetSymbolAddress((void**)&p_xfar,   g_xfar);
    cudaGetSymbolAddress((void**)&p_q,      g_q);
    cudaGetSymbolAddress((void**)&p_k,      g_kmat);
    cudaGetSymbolAddress((void**)&p_v,      g_v);
    cudaGetSymbolAddress((void**)&p_ao,     g_ao);
    cudaGetSymbolAddress((void**)&p_proj,   g_proj);

    const long long AKC = (long long)KK * CC;
    const long long AMC = (long long)MM * CC;
    const long long ANK = (long long)NN * KK;
    const long long ANC = (long long)NN * CC;

    k_zero<<<512, 256>>>();

    // to_basis 1: full N, split-K over 32 chunks of 1024
    k_tobasis_mma<<<dim3(32, 4, BB), 256, TOB_SMEM>>>(x, mass, evecs, nullptr, p_spec1, 1024, NN);
    k_coef<<<BB*KK, CC>>>(evals, t_in, p_spec1, p_spec1m, nullptr);

    // from_basis 1: only the M gathered rows
    k_gemm_mma<<<dim3(MM/128, 4, BB), 256, GEMM_SMEM>>>(
        evecs, far_idx, ANK,
        p_spec1m, nullptr, nullptr, AKC,
        nullptr, nullptr, nullptr,
        p_xfar, nullptr, nullptr, AMC, KK, 1);

    // GroupNorm
    k_gnstats<<<BB*GG, 256>>>();
    k_gnapply<<<(BB*MM*CC/4)/256, 256>>>(gn_w, gn_b);

    // QKV projections fused (nW=3)
    k_gemm_mma<<<dim3(MM/128, 4, BB*3), 256, GEMM_SMEM>>>(
        p_xfar, nullptr, AMC,
        Wq, Wk, Wv, 0,
        bq, bk, bv,
        p_q, p_k, p_v, AMC, CC, 3);

    // attention (tensor-core flash)
    k_attn_mma<<<dim3(MM/64, HH, BB), 256, ATT_SMEM>>>();

    // output projection
    k_gemm_mma<<<dim3(MM/128, 4, BB), 256, GEMM_SMEM>>>(
        p_ao, nullptr, AMC,
        Wo, nullptr, nullptr, 0,
        bo, nullptr, nullptr,
        p_proj, nullptr, nullptr, AMC, CC, 1);

    // to_basis 2: only the M scattered rows
    k_tobasis_mma<<<dim3(8, 4, BB), 256, TOB_SMEM>>>(p_proj, mass, evecs, far_idx, p_spec2, 128, MM);
    k_coef<<<BB*KK, CC>>>(evals, t_out, p_spec2, p_spec2m, out_w);

    // from_basis 2: full N output (out_w folded into spec2m)
    k_gemm_mma<<<dim3(NN/128, 4, BB), 256, GEMM_SMEM>>>(
        evecs, nullptr, ANK,
        p_spec2m, nullptr, nullptr, AKC,
        nullptr, nullptr, nullptr,
        out, nullptr, nullptr, ANC, KK, 1);
}

// round 10
// speedup vs baseline: 1.9839x; 1.0458x over previous
#include <cuda_runtime.h>
#include <math.h>
#include <stdint.h>

#define BB 4
#define NN 32768
#define KK 128
#define MM 1024
#define CC 256
#define GG 32
#define HH 8
#define DD 32

// ---------------- scratch (device globals; no allocation allowed) ----------------
__device__ float g_spec1 [BB*KK*CC];
__device__ float g_spec1m[BB*KK*CC];
__device__ float g_spec2 [BB*KK*CC];
__device__ float g_spec2m[BB*KK*CC];
__device__ float g_xfar  [BB*MM*CC];
__device__ float g_q     [BB*MM*CC];
__device__ float g_kmat  [BB*MM*CC];
__device__ float g_v     [BB*MM*CC];
__device__ float g_ao    [BB*MM*CC];
__device__ float g_proj  [BB*MM*CC];
__device__ float g_gnm   [BB*GG];
__device__ float g_gnr   [BB*GG];

// ---------------- tf32 helpers ----------------
__device__ __forceinline__ float tf32r(float x) {
    uint32_t u; asm("cvt.rna.tf32.f32 %0, %1;" : "=r"(u) : "f"(x));
    return __uint_as_float(u);
}

__device__ __forceinline__ void mma8(float d[4], const uint32_t a[4],
                                     uint32_t b0, uint32_t b1) {
    asm volatile(
        "mma.sync.aligned.m16n8k8.row.col.f32.tf32.tf32.f32 "
        "{%0,%1,%2,%3},{%4,%5,%6,%7},{%8,%9},{%0,%1,%2,%3};\n"
        : "+f"(d[0]), "+f"(d[1]), "+f"(d[2]), "+f"(d[3])
        : "r"(a[0]), "r"(a[1]), "r"(a[2]), "r"(a[3]), "r"(b0), "r"(b1));
}

// ---------------- zero the atomic accumulators ----------------
__global__ void k_zero() {
    int i = blockIdx.x * blockDim.x + threadIdx.x;
    if (i < BB*KK*CC) { g_spec1[i] = 0.f; g_spec2[i] = 0.f; }
}

// =====================================================================
// to_basis via 3x-tf32 mma, raw-fp32 smem + register hi/lo split.
// (unchanged from round 9 — proven)
// =====================================================================
#define TOB_SMEM_FLOATS (2*16*136 + 2*16*72)   // 6656 floats = 26624 B

__global__ void __launch_bounds__(256,2) k_tobasis_mma(
    const float* __restrict__ X, const float* __restrict__ mass,
    const float* __restrict__ evecs, const int* __restrict__ gidx,
    float* __restrict__ spec, int chunk, int xRowsPerBatch)
{
    extern __shared__ float sm[];
    float* sE = sm;                 // [2][16][136]
    float* sX = sE + 2*16*136;      // [2][16][72]
#define SE(bf,r,c) sE[(bf)*2176 + (r)*136 + (c)]
#define SX(bf,r,c) sX[(bf)*1152 + (r)*72 + (c)]

    int b  = blockIdx.z;
    int c0 = blockIdx.y * 64;
    int n0 = blockIdx.x * chunk;
    int tid  = threadIdx.x;
    int wid  = tid >> 5, lane = tid & 31;
    int wm   = wid & 3;
    int wn   = wid >> 2;
    int lrow = lane >> 2;
    int lcol = lane & 3;

    int iters = chunk >> 4;

    int er0 = tid >> 5,         ec0 = tid & 31;
    int er1 = (tid + 256) >> 5, ec1 = (tid + 256) & 31;
    int xr  = tid >> 4,         xc  = tid & 15;

    float4 pe0, pe1, px; float pm;
    float4 qe0, qe1, qx; float qm;

#define TOB_FETCH(it, e0, e1, xv, ms) {                                        \
        int n = n0 + ((it) << 4) + er0;                                        \
        int rr = gidx ? gidx[b*MM + n] : n;                                    \
        e0 = *reinterpret_cast<const float4*>(&evecs[((size_t)b*NN + rr)*KK + ec0*4]); \
        n = n0 + ((it) << 4) + er1;                                            \
        rr = gidx ? gidx[b*MM + n] : n;                                        \
        e1 = *reinterpret_cast<const float4*>(&evecs[((size_t)b*NN + rr)*KK + ec1*4]); \
        n = n0 + ((it) << 4) + xr;                                             \
        rr = gidx ? gidx[b*MM + n] : n;                                        \
        ms = mass[(size_t)b*NN + rr];                                          \
        xv = *reinterpret_cast<const float4*>(&X[((size_t)b*xRowsPerBatch + n)*CC + c0 + xc*4]); \
    }

#define TOB_STS(bf, e0, e1, xv, ms) {                                          \
        *reinterpret_cast<float4*>(&SE(bf, er0, ec0*4)) = e0;                  \
        *reinterpret_cast<float4*>(&SE(bf, er1, ec1*4)) = e1;                  \
        float4 xs = xv;                                                        \
        xs.x *= ms; xs.y *= ms; xs.z *= ms; xs.w *= ms;                        \
        *reinterpret_cast<float4*>(&SX(bf, xr, xc*4)) = xs;                    \
    }

    float acc[2][4][4];
#pragma unroll
    for (int mt = 0; mt < 2; mt++)
#pragma unroll
        for (int nt = 0; nt < 4; nt++)
#pragma unroll
            for (int j = 0; j < 4; j++) acc[mt][nt][j] = 0.f;

    TOB_FETCH(0, pe0, pe1, px, pm);
    TOB_STS(0, pe0, pe1, px, pm);
    if (iters > 1) TOB_FETCH(1, pe0, pe1, px, pm);
    __syncthreads();

    for (int i = 0; i < iters; i++) {
        int cur = i & 1;
        if (i + 2 < iters) TOB_FETCH(i + 2, qe0, qe1, qx, qm);
        if (i + 1 < iters) TOB_STS(cur ^ 1, pe0, pe1, px, pm);

#pragma unroll
        for (int ks = 0; ks < 2; ks++) {
            int kf = ks*8 + lcol;
            uint32_t Aih[2][4], Ail[2][4];
#pragma unroll
            for (int mt = 0; mt < 2; mt++) {
                int m = wm*32 + mt*16 + lrow;
                float r0 = SE(cur, kf,   m);
                float r1 = SE(cur, kf,   m+8);
                float r2 = SE(cur, kf+4, m);
                float r3 = SE(cur, kf+4, m+8);
                float h0 = tf32r(r0), h1 = tf32r(r1), h2 = tf32r(r2), h3 = tf32r(r3);
                Aih[mt][0] = __float_as_uint(h0);
                Aih[mt][1] = __float_as_uint(h1);
                Aih[mt][2] = __float_as_uint(h2);
                Aih[mt][3] = __float_as_uint(h3);
                Ail[mt][0] = __float_as_uint(r0 - h0);
                Ail[mt][1] = __float_as_uint(r1 - h1);
                Ail[mt][2] = __float_as_uint(r2 - h2);
                Ail[mt][3] = __float_as_uint(r3 - h3);
            }
#pragma unroll
            for (int nt = 0; nt < 4; nt++) {
                int c = wn*32 + nt*8 + lrow;
                float b0r = SX(cur, kf,   c);
                float b1r = SX(cur, kf+4, c);
                float hb0 = tf32r(b0r), hb1 = tf32r(b1r);
                uint32_t bh0 = __float_as_uint(hb0);
                uint32_t bh1 = __float_as_uint(hb1);
                uint32_t bl0 = __float_as_uint(b0r - hb0);
                uint32_t bl1 = __float_as_uint(b1r - hb1);
#pragma unroll
                for (int mt = 0; mt < 2; mt++) {
                    mma8(acc[mt][nt], Aih[mt], bh0, bh1);
                    mma8(acc[mt][nt], Aih[mt], bl0, bl1);
                    mma8(acc[mt][nt], Ail[mt], bh0, bh1);
                }
            }
        }
        __syncthreads();
        pe0 = qe0; pe1 = qe1; px = qx; pm = qm;
    }

#pragma unroll
    for (int mt = 0; mt < 2; mt++) {
#pragma unroll
        for (int nt = 0; nt < 4; nt++) {
            int row0 = wm*32 + mt*16 + lrow;
            int col  = c0 + wn*32 + nt*8 + 2*lcol;
            float* p0 = &spec[((size_t)b*KK + row0    ) * CC + col];
            float* p1 = &spec[((size_t)b*KK + row0 + 8) * CC + col];
            atomicAdd(p0,     acc[mt][nt][0]);
            atomicAdd(p0 + 1, acc[mt][nt][1]);
            atomicAdd(p1,     acc[mt][nt][2]);
            atomicAdd(p1 + 1, acc[mt][nt][3]);
        }
    }
}

// =====================================================================
// generic 3x-tf32 mma GEMM, raw-fp32 smem + register hi/lo split.
// (unchanged from round 9 — proven)
// =====================================================================
#define GEMM_SMEM_FLOATS (2*128*20 + 2*16*72)   // 7424 floats = 29696 B

__global__ void __launch_bounds__(256,2) k_gemm_mma(
    const float* __restrict__ A, const int* __restrict__ gidx, long long aBatch,
    const float* __restrict__ W0, const float* __restrict__ W1,
    const float* __restrict__ W2, long long wBatch,
    const float* __restrict__ bias0, const float* __restrict__ bias1,
    const float* __restrict__ bias2,
    float* __restrict__ out0, float* __restrict__ out1, float* __restrict__ out2,
    long long oBatch, int Kd, int nW)
{
    extern __shared__ float sm[];
    float* sA = sm;                 // [2][128][20]
    float* sB = sA + 2*128*20;      // [2][16][72]
#define SA(bf,r,k) sA[(bf)*2560 + (r)*20 + (k)]
#define SB(bf,r,c) sB[(bf)*1152 + (r)*72 + (c)]

    int z   = blockIdx.z;
    int b   = z / nW;
    int sel = z - b * nW;
    int r0  = blockIdx.x * 128;
    int c0  = blockIdx.y * 64;

    const float* W    = (sel == 0) ? W0    : (sel == 1) ? W1    : W2;
    const float* bias = (sel == 0) ? bias0 : (sel == 1) ? bias1 : bias2;
    float*       out  = (sel == 0) ? out0  : (sel == 1) ? out1  : out2;

    int tid  = threadIdx.x;
    int wid  = tid >> 5, lane = tid & 31;
    int wm   = wid & 3;
    int wn   = wid >> 2;
    int lrow = lane >> 2;
    int lcol = lane & 3;

    const float* Ab = A + (size_t)b * aBatch;
    const float* Wb = W + (size_t)b * wBatch;
    float*       Ob = out + (size_t)b * oBatch;

    int iters = Kd >> 4;

    int ar0 = tid >> 2,         ak0 = tid & 3;
    int ar1 = (tid + 256) >> 2, ak1 = (tid + 256) & 3;
    int br  = tid >> 4,         bc  = tid & 15;
    int ga0 = gidx ? gidx[b*MM + r0 + ar0] : (r0 + ar0);
    int ga1 = gidx ? gidx[b*MM + r0 + ar1] : (r0 + ar1);

    float4 pa0, pa1, pw;
    float4 qa0, qa1, qw;

#define G_FETCH(it, a0, a1, wv) {                                              \
        int kc = (it) << 4;                                                    \
        a0 = *reinterpret_cast<const float4*>(Ab + (size_t)ga0 * Kd + kc + ak0*4); \
        a1 = *reinterpret_cast<const float4*>(Ab + (size_t)ga1 * Kd + kc + ak1*4); \
        wv = *reinterpret_cast<const float4*>(Wb + (size_t)(kc + br) * CC + c0 + bc*4); \
    }

#define G_STS(bf, a0, a1, wv) {                                                \
        *reinterpret_cast<float4*>(&SA(bf, ar0, ak0*4)) = a0;                  \
        *reinterpret_cast<float4*>(&SA(bf, ar1, ak1*4)) = a1;                  \
        *reinterpret_cast<float4*>(&SB(bf, br, bc*4)) = wv;                    \
    }

    float acc[2][4][4];
#pragma unroll
    for (int mt = 0; mt < 2; mt++)
#pragma unroll
        for (int nt = 0; nt < 4; nt++)
#pragma unroll
            for (int j = 0; j < 4; j++) acc[mt][nt][j] = 0.f;

    G_FETCH(0, pa0, pa1, pw);
    G_STS(0, pa0, pa1, pw);
    if (iters > 1) G_FETCH(1, pa0, pa1, pw);
    __syncthreads();

    for (int i = 0; i < iters; i++) {
        int cur = i & 1;
        if (i + 2 < iters) G_FETCH(i + 2, qa0, qa1, qw);
        if (i + 1 < iters) G_STS(cur ^ 1, pa0, pa1, pw);

#pragma unroll
        for (int ks = 0; ks < 2; ks++) {
            int kf = ks*8 + lcol;
            uint32_t Aih[2][4], Ail[2][4];
#pragma unroll
            for (int mt = 0; mt < 2; mt++) {
                int m = wm*32 + mt*16 + lrow;
                float r0 = SA(cur, m,   kf);
                float r1 = SA(cur, m+8, kf);
                float r2 = SA(cur, m,   kf+4);
                float r3 = SA(cur, m+8, kf+4);
                float h0 = tf32r(r0), h1 = tf32r(r1), h2 = tf32r(r2), h3 = tf32r(r3);
                Aih[mt][0] = __float_as_uint(h0);
                Aih[mt][1] = __float_as_uint(h1);
                Aih[mt][2] = __float_as_uint(h2);
                Aih[mt][3] = __float_as_uint(h3);
                Ail[mt][0] = __float_as_uint(r0 - h0);
                Ail[mt][1] = __float_as_uint(r1 - h1);
                Ail[mt][2] = __float_as_uint(r2 - h2);
                Ail[mt][3] = __float_as_uint(r3 - h3);
            }
#pragma unroll
            for (int nt = 0; nt < 4; nt++) {
                int c = wn*32 + nt*8 + lrow;
                float b0r = SB(cur, kf,   c);
                float b1r = SB(cur, kf+4, c);
                float hb0 = tf32r(b0r), hb1 = tf32r(b1r);
                uint32_t bh0 = __float_as_uint(hb0);
                uint32_t bh1 = __float_as_uint(hb1);
                uint32_t bl0 = __float_as_uint(b0r - hb0);
                uint32_t bl1 = __float_as_uint(b1r - hb1);
#pragma unroll
                for (int mt = 0; mt < 2; mt++) {
                    mma8(acc[mt][nt], Aih[mt], bh0, bh1);
                    mma8(acc[mt][nt], Aih[mt], bl0, bl1);
                    mma8(acc[mt][nt], Ail[mt], bh0, bh1);
                }
            }
        }
        __syncthreads();
        pa0 = qa0; pa1 = qa1; pw = qw;
    }

#pragma unroll
    for (int mt = 0; mt < 2; mt++) {
#pragma unroll
        for (int nt = 0; nt < 4; nt++) {
            int row0 = r0 + wm*32 + mt*16 + lrow;
            int col  = c0 + wn*32 + nt*8 + 2*lcol;
            float b0v = bias ? bias[col]     : 0.f;
            float b1v = bias ? bias[col + 1] : 0.f;
            float2 v0 = {acc[mt][nt][0] + b0v, acc[mt][nt][1] + b1v};
            float2 v1 = {acc[mt][nt][2] + b0v, acc[mt][nt][3] + b1v};
            *reinterpret_cast<float2*>(&Ob[(size_t)row0       * CC + col]) = v0;
            *reinterpret_cast<float2*>(&Ob[(size_t)(row0 + 8) * CC + col]) = v1;
        }
    }
}

// ---------------- spectral coefficient multiply (+ optional out_w fold) ----------------
__global__ void k_coef(const float* __restrict__ evals, const float* __restrict__ tvec,
                       const float* __restrict__ specin, float* __restrict__ specout,
                       const float* __restrict__ outw)
{
    int bk = blockIdx.x;
    int b = bk >> 7, k = bk & 127;
    int c = threadIdx.x;
    float t = fmaxf(tvec[c], 1e-8f);
    float w = outw ? fmaxf(outw[c], 1e-8f) : 1.f;
    specout[(size_t)bk*CC + c] = expf(-evals[b*KK + k] * t) * specin[(size_t)bk*CC + c] * w;
}

// ---------------- GroupNorm stats ----------------
__global__ void k_gnstats()
{
    int b = blockIdx.x >> 5, g = blockIdx.x & 31;
    int tid = threadIdx.x;
    float s = 0.f, s2 = 0.f;
    for (int e = tid; e < MM*8; e += 256) {
        int m = e >> 3, j = e & 7;
        float v = g_xfar[((size_t)(b*MM + m)) * CC + (g << 3) + j];
        s += v; s2 += v * v;
    }
    __shared__ float rs[256], rq[256];
    rs[tid] = s; rq[tid] = s2;
    __syncthreads();
    for (int o = 128; o > 0; o >>= 1) {
        if (tid < o) { rs[tid] += rs[tid+o]; rq[tid] += rq[tid+o]; }
        __syncthreads();
    }
    if (tid == 0) {
        float mean = rs[0] * (1.f/8192.f);
        float var  = rq[0] * (1.f/8192.f) - mean*mean;
        g_gnm[blockIdx.x] = mean;
        g_gnr[blockIdx.x] = rsqrtf(var + 1e-6f);
    }
}

// ---------------- GroupNorm apply (in place) ----------------
__global__ void k_gnapply(const float* __restrict__ gn_w, const float* __restrict__ gn_b)
{
    int i = blockIdx.x * blockDim.x + threadIdx.x;
    int base = i * 4;
    int c  = base & 255;
    int bm = base >> 8;
    int b  = bm >> 10;
    int g  = c >> 3;
    float mean = g_gnm[b*GG + g];
    float r    = g_gnr[b*GG + g];
    float4 v = *reinterpret_cast<float4*>(&g_xfar[base]);
    v.x = (v.x - mean) * r * gn_w[c+0] + gn_b[c+0];
    v.y = (v.y - mean) * r * gn_w[c+1] + gn_b[c+1];
    v.z = (v.z - mean) * r * gn_w[c+2] + gn_b[c+2];
    v.w = (v.w - mean) * r * gn_w[c+3] + gn_b[c+3];
    *reinterpret_cast<float4*>(&g_xfar[base]) = v;
}

// =====================================================================
// flash attention with 3x-tf32 mma, raw-fp32 smem + register hi/lo split.
// 64-query tiles, 16 key tiles of 64, online softmax.
// smem (single raw copies): K^T [32][69], V [64][40], P/Q [64][68]
// =====================================================================
#define ATT_KP 69
#define ATT_VP 40
#define ATT_PP 68
#define ATT_QP 36
#define ATT_SMEM_FLOATS (32*ATT_KP + 64*ATT_VP + 64*ATT_PP + 256)   // 9376 floats

__global__ void __launch_bounds__(256,2) k_attn_mma()
{
    extern __shared__ float sm[];
    float* sK  = sm;                        // [32][69] raw, transposed [d][key]
    float* sV  = sK + 32*ATT_KP;            // [64][40] raw
    float* sP  = sV + 64*ATT_VP;            // [64][68] raw (Q staging [64][36])
    float* sRm = sP + 64*ATT_PP;            // [2][64]
    float* sRl = sRm + 128;                 // [2][64]

    int b = blockIdx.z, h = blockIdx.y, q0 = blockIdx.x * 64;
    int tid = threadIdx.x;
    int wid = tid >> 5, lane = tid & 31;
    int wm = wid & 3, wn = wid >> 2;
    int lrow = lane >> 2, lcol = lane & 3;
    const float scale = 0.17677669529663687f;   // 1/sqrt(32)
    const float L2E = 1.4426950408889634f;

    // ---- stage Q (scaled) raw into P region as [64][36] ----
#pragma unroll
    for (int v = tid; v < 512; v += 256) {
        int r = v >> 3, d0 = (v & 7) * 4;
        float4 qv = *reinterpret_cast<const float4*>(
            &g_q[((size_t)(b*MM) + q0 + r) * CC + h*DD + d0]);
        qv.x *= scale; qv.y *= scale; qv.z *= scale; qv.w *= scale;
        *reinterpret_cast<float4*>(&sP[r*ATT_QP + d0]) = qv;
    }
    __syncthreads();

    // hoist Q fragments to registers, splitting hi/lo in-register
    uint32_t Aqh[4][4], Aql[4][4];
    {
        int m = 16*wm + lrow;
#pragma unroll
        for (int ks = 0; ks < 4; ks++) {
            int kf = ks*8 + lcol;
            float r0 = sP[m*ATT_QP + kf];
            float r1 = sP[(m+8)*ATT_QP + kf];
            float r2 = sP[m*ATT_QP + kf + 4];
            float r3 = sP[(m+8)*ATT_QP + kf + 4];
            float h0 = tf32r(r0), h1 = tf32r(r1), h2 = tf32r(r2), h3 = tf32r(r3);
            Aqh[ks][0] = __float_as_uint(h0);
            Aqh[ks][1] = __float_as_uint(h1);
            Aqh[ks][2] = __float_as_uint(h2);
            Aqh[ks][3] = __float_as_uint(h3);
            Aql[ks][0] = __float_as_uint(r0 - h0);
            Aql[ks][1] = __float_as_uint(r1 - h1);
            Aql[ks][2] = __float_as_uint(r2 - h2);
            Aql[ks][3] = __float_as_uint(r3 - h3);
        }
    }

    float oacc[2][4];
#pragma unroll
    for (int nt = 0; nt < 2; nt++)
#pragma unroll
        for (int j = 0; j < 4; j++) oacc[nt][j] = 0.f;
    float mrun0 = -1e30f, mrun1 = -1e30f, lrun0 = 0.f, lrun1 = 0.f;
    int rbase = 16*wm + lrow;

    for (int kt = 0; kt < 16; kt++) {
        __syncthreads();   // previous tile's smem reads done
        // ---- load K (raw, transposed) and V (raw) ----
#pragma unroll
        for (int v = tid; v < 512; v += 256) {
            int r = v >> 3, d0 = (v & 7) * 4;
            size_t gi = ((size_t)b*MM + kt*64 + r) * CC + h*DD + d0;
            float4 kv = *reinterpret_cast<const float4*>(&g_kmat[gi]);
            sK[(d0+0)*ATT_KP + r] = kv.x;
            sK[(d0+1)*ATT_KP + r] = kv.y;
            sK[(d0+2)*ATT_KP + r] = kv.z;
            sK[(d0+3)*ATT_KP + r] = kv.w;
            float4 vv = *reinterpret_cast<const float4*>(&g_v[gi]);
            *reinterpret_cast<float4*>(&sV[r*ATT_VP + d0]) = vv;
        }
        __syncthreads();

        // ---- QK^T mma (raw K frags, reg split) ----
        float s[4][4];
#pragma unroll
        for (int nt = 0; nt < 4; nt++)
#pragma unroll
            for (int j = 0; j < 4; j++) s[nt][j] = 0.f;
#pragma unroll
        for (int ks = 0; ks < 4; ks++) {
            int kf = ks*8 + lcol;
#pragma unroll
            for (int nt = 0; nt < 4; nt++) {
                int key = wn*32 + nt*8 + lrow;
                float b0r = sK[kf*ATT_KP + key];
                float b1r = sK[(kf+4)*ATT_KP + key];
                float hb0 = tf32r(b0r), hb1 = tf32r(b1r);
                uint32_t bh0 = __float_as_uint(hb0);
                uint32_t bh1 = __float_as_uint(hb1);
                uint32_t bl0 = __float_as_uint(b0r - hb0);
                uint32_t bl1 = __float_as_uint(b1r - hb1);
                mma8(s[nt], Aqh[ks], bh0, bh1);
                mma8(s[nt], Aqh[ks], bl0, bl1);
                mma8(s[nt], Aql[ks], bh0, bh1);
            }
        }

        // ---- row max ----
        float t0 = -1e30f, t1 = -1e30f;
#pragma unroll
        for (int nt = 0; nt < 4; nt++) {
            t0 = fmaxf(t0, fmaxf(s[nt][0], s[nt][1]));
            t1 = fmaxf(t1, fmaxf(s[nt][2], s[nt][3]));
        }
        t0 = fmaxf(t0, __shfl_xor_sync(0xffffffff, t0, 1));
        t0 = fmaxf(t0, __shfl_xor_sync(0xffffffff, t0, 2));
        t1 = fmaxf(t1, __shfl_xor_sync(0xffffffff, t1, 1));
        t1 = fmaxf(t1, __shfl_xor_sync(0xffffffff, t1, 2));
        if (lcol == 0) {
            sRm[wn*64 + rbase]     = t0;
            sRm[wn*64 + rbase + 8] = t1;
        }
        __syncthreads();
        float mnew0 = fmaxf(mrun0, fmaxf(sRm[rbase],     sRm[64 + rbase]));
        float mnew1 = fmaxf(mrun1, fmaxf(sRm[rbase + 8], sRm[64 + rbase + 8]));

        // ---- exp, partial sums, write raw P ----
        float ls0 = 0.f, ls1 = 0.f;
#pragma unroll
        for (int nt = 0; nt < 4; nt++) {
            float p0 = exp2f((s[nt][0] - mnew0) * L2E);
            float p1 = exp2f((s[nt][1] - mnew0) * L2E);
            float p2 = exp2f((s[nt][2] - mnew1) * L2E);
            float p3 = exp2f((s[nt][3] - mnew1) * L2E);
            ls0 += p0 + p1;
            ls1 += p2 + p3;
            int col = wn*32 + nt*8 + 2*lcol;
            float2 w0 = {p0, p1}, w1 = {p2, p3};
            *reinterpret_cast<float2*>(&sP[rbase*ATT_PP + col])     = w0;
            *reinterpret_cast<float2*>(&sP[(rbase+8)*ATT_PP + col]) = w1;
        }
        ls0 += __shfl_xor_sync(0xffffffff, ls0, 1);
        ls0 += __shfl_xor_sync(0xffffffff, ls0, 2);
        ls1 += __shfl_xor_sync(0xffffffff, ls1, 1);
        ls1 += __shfl_xor_sync(0xffffffff, ls1, 2);
        if (lcol == 0) {
            sRl[wn*64 + rbase]     = ls0;
            sRl[wn*64 + rbase + 8] = ls1;
        }
        __syncthreads();
        float lt0 = sRl[rbase]     + sRl[64 + rbase];
        float lt1 = sRl[rbase + 8] + sRl[64 + rbase + 8];
        float c0 = exp2f((mrun0 - mnew0) * L2E);
        float c1 = exp2f((mrun1 - mnew1) * L2E);
        lrun0 = lrun0 * c0 + lt0;
        lrun1 = lrun1 * c1 + lt1;
        mrun0 = mnew0; mrun1 = mnew1;
#pragma unroll
        for (int nt = 0; nt < 2; nt++) {
            oacc[nt][0] *= c0; oacc[nt][1] *= c0;
            oacc[nt][2] *= c1; oacc[nt][3] *= c1;
        }

        // ---- P*V mma (raw frags, reg split) ----
#pragma unroll
        for (int ks = 0; ks < 8; ks++) {
            int kf = ks*8 + lcol;
            float r0 = sP[rbase*ATT_PP + kf];
            float r1 = sP[(rbase+8)*ATT_PP + kf];
            float r2 = sP[rbase*ATT_PP + kf + 4];
            float r3 = sP[(rbase+8)*ATT_PP + kf + 4];
            float h0 = tf32r(r0), h1 = tf32r(r1), h2 = tf32r(r2), h3 = tf32r(r3);
            uint32_t Aph[4], Apl[4];
            Aph[0] = __float_as_uint(h0);
            Aph[1] = __float_as_uint(h1);
            Aph[2] = __float_as_uint(h2);
            Aph[3] = __float_as_uint(h3);
            Apl[0] = __float_as_uint(r0 - h0);
            Apl[1] = __float_as_uint(r1 - h1);
            Apl[2] = __float_as_uint(r2 - h2);
            Apl[3] = __float_as_uint(r3 - h3);
#pragma unroll
            for (int nt = 0; nt < 2; nt++) {
                int d = wn*16 + nt*8 + lrow;
                float b0r = sV[kf*ATT_VP + d];
                float b1r = sV[(kf+4)*ATT_VP + d];
                float hb0 = tf32r(b0r), hb1 = tf32r(b1r);
                uint32_t bh0 = __float_as_uint(hb0);
                uint32_t bh1 = __float_as_uint(hb1);
                uint32_t bl0 = __float_as_uint(b0r - hb0);
                uint32_t bl1 = __float_as_uint(b1r - hb1);
                mma8(oacc[nt], Aph, bh0, bh1);
                mma8(oacc[nt], Aph, bl0, bl1);
                mma8(oacc[nt], Apl, bh0, bh1);
            }
        }
    }

    // ---- write output ----
    float i0 = 1.f / lrun0, i1 = 1.f / lrun1;
#pragma unroll
    for (int nt = 0; nt < 2; nt++) {
        int col = h*DD + wn*16 + nt*8 + 2*lcol;
        size_t o0 = ((size_t)(b*MM) + q0 + rbase) * CC + col;
        size_t o1 = ((size_t)(b*MM) + q0 + rbase + 8) * CC + col;
        float2 w0 = {oacc[nt][0]*i0, oacc[nt][1]*i0};
        float2 w1 = {oacc[nt][2]*i1, oacc[nt][3]*i1};
        *reinterpret_cast<float2*>(&g_ao[o0]) = w0;
        *reinterpret_cast<float2*>(&g_ao[o1]) = w1;
    }
}

// ---------------- launch ----------------
extern "C" void kernel_launch(void* const* d_in, const int* in_sizes, int n_in,
                              void* d_out, int out_size)
{
    const float* x       = (const float*)d_in[0];
    const float* mass    = (const float*)d_in[1];
    const float* evals   = (const float*)d_in[2];
    const float* evecs   = (const float*)d_in[3];
    const int*   far_idx = (const int*)  d_in[4];
    const float* t_in    = (const float*)d_in[5];
    const float* t_out   = (const float*)d_in[6];
    const float* gn_w    = (const float*)d_in[7];
    const float* gn_b    = (const float*)d_in[8];
    const float* Wq      = (const float*)d_in[9];
    const float* bq      = (const float*)d_in[10];
    const float* Wk      = (const float*)d_in[11];
    const float* bk      = (const float*)d_in[12];
    const float* Wv      = (const float*)d_in[13];
    const float* bv      = (const float*)d_in[14];
    const float* Wo      = (const float*)d_in[15];
    const float* bo      = (const float*)d_in[16];
    const float* out_w   = (const float*)d_in[17];
    float* out = (float*)d_out;

    static int s_attr_done = 0;
    const int TOB_SMEM  = TOB_SMEM_FLOATS  * 4;
    const int GEMM_SMEM = GEMM_SMEM_FLOATS * 4;
    const int ATT_SMEM  = ATT_SMEM_FLOATS  * 4;
    if (!s_attr_done) {
        cudaFuncSetAttribute(k_tobasis_mma, cudaFuncAttributeMaxDynamicSharedMemorySize, TOB_SMEM);
        cudaFuncSetAttribute(k_gemm_mma,    cudaFuncAttributeMaxDynamicSharedMemorySize, GEMM_SMEM);
        cudaFuncSetAttribute(k_attn_mma,    cudaFuncAttributeMaxDynamicSharedMemorySize, ATT_SMEM);
        s_attr_done = 1;
    }

    float *p_spec1, *p_spec1m, *p_spec2, *p_spec2m, *p_xfar, *p_q, *p_k, *p_v, *p_ao, *p_proj;
    cudaGetSymbolAddress((void**)&p_spec1,  g_spec1);
    cudaGetSymbolAddress((void**)&p_spec1m, g_spec1m);
    cudaGetSymbolAddress((void**)&p_spec2,  g_spec2);
    cudaGetSymbolAddress((void**)&p_spec2m, g_spec2m);
    cudaGetSymbolAddress((void**)&p_xfar,   g_xfar);
    cudaGetSymbolAddress((void**)&p_q,      g_q);
    cudaGetSymbolAddress((void**)&p_k,      g_kmat);
    cudaGetSymbolAddress((void**)&p_v,      g_v);
    cudaGetSymbolAddress((void**)&p_ao,     g_ao);
    cudaGetSymbolAddress((void**)&p_proj,   g_proj);

    const long long AKC = (long long)KK * CC;
    const long long AMC = (long long)MM * CC;
    const long long ANK = (long long)NN * KK;
    const long long ANC = (long long)NN * CC;

    k_zero<<<512, 256>>>();

    // to_basis 1: full N, split-K over 32 chunks of 1024
    k_tobasis_mma<<<dim3(32, 4, BB), 256, TOB_SMEM>>>(x, mass, evecs, nullptr, p_spec1, 1024, NN);
    k_coef<<<BB*KK, CC>>>(evals, t_in, p_spec1, p_spec1m, nullptr);

    // from_basis 1: only the M gathered rows
    k_gemm_mma<<<dim3(MM/128, 4, BB), 256, GEMM_SMEM>>>(
        evecs, far_idx, ANK,
        p_spec1m, nullptr, nullptr, AKC,
        nullptr, nullptr, nullptr,
        p_xfar, nullptr, nullptr, AMC, KK, 1);

    // GroupNorm
    k_gnstats<<<BB*GG, 256>>>();
    k_gnapply<<<(BB*MM*CC/4)/256, 256>>>(gn_w, gn_b);

    // QKV projections fused (nW=3)
    k_gemm_mma<<<dim3(MM/128, 4, BB*3), 256, GEMM_SMEM>>>(
        p_xfar, nullptr, AMC,
        Wq, Wk, Wv, 0,
        bq, bk, bv,
        p_q, p_k, p_v, AMC, CC, 3);

    // attention (tensor-core flash, raw smem)
    k_attn_mma<<<dim3(MM/64, HH, BB), 256, ATT_SMEM>>>();

    // output projection
    k_gemm_mma<<<dim3(MM/128, 4, BB), 256, GEMM_SMEM>>>(
        p_ao, nullptr, AMC,
        Wo, nullptr, nullptr, 0,
        bo, nullptr, nullptr,
        p_proj, nullptr, nullptr, AMC, CC, 1);

    // to_basis 2: only the M scattered rows
    k_tobasis_mma<<<dim3(8, 4, BB), 256, TOB_SMEM>>>(p_proj, mass, evecs, far_idx, p_spec2, 128, MM);
    k_coef<<<BB*KK, CC>>>(evals, t_out, p_spec2, p_spec2m, out_w);

    // from_basis 2: full N output (out_w folded into spec2m)
    k_gemm_mma<<<dim3(NN/128, 4, BB), 256, GEMM_SMEM>>>(
        evecs, nullptr, ANK,
        p_spec2m, nullptr, nullptr, AKC,
        nullptr, nullptr, nullptr,
        out, nullptr, nullptr, ANC, KK, 1);
}